// round 8
// baseline (speedup 1.0000x reference)
#include <cuda_runtime.h>
#include <cstdint>

typedef unsigned long long ull;

#define BB 2
#define NN 768
#define CS 768
#define HH 16
#define HD 48
#define CZ 128

#define IT 64      // attention i-tile rows
#define JT 64      // attention j-tile cols
#define PST 68     // ps_T row stride (floats): [64 k][PST], 16B-aligned rows

// ----- scratch (static device globals: no allocation allowed) -----
__device__ float g_q [BB*NN*CS];
__device__ float g_k [BB*NN*CS];
__device__ float g_v [BB*NN*CS];
__device__ float g_g [BB*NN*CS];
__device__ float g_og[BB*NN*CS];
__device__ float g_bias[(size_t)BB*HH*NN*NN];

// ----- packed f32x2 helpers -----
__device__ __forceinline__ ull pack2(float x, float y) {
    ull r; asm("mov.b64 %0, {%1, %2};" : "=l"(r) : "f"(x), "f"(y)); return r;
}
__device__ __forceinline__ ull dup2(float x) { return pack2(x, x); }
__device__ __forceinline__ void fma2(ull& d, ull a, ull b) {
    asm("fma.rn.f32x2 %0, %1, %2, %0;" : "+l"(d) : "l"(a), "l"(b));
}
__device__ __forceinline__ void mul2(ull& d, ull a) {
    asm("mul.rn.f32x2 %0, %0, %1;" : "+l"(d) : "l"(a));
}
__device__ __forceinline__ void unpack2(ull v, float& x, float& y) {
    asm("mov.b64 {%0, %1}, %2;" : "=f"(x), "=f"(y) : "l"(v));
}

// ----- 64x64 tiled GEMM, BK=32, 256 threads, 4x4/thread, reg prefetch -----
// C[m][n] = sum_k A[m][k]*W[n][k] (+bias, opt sigmoid)
__device__ __forceinline__ void gemm_block64(
    const float* __restrict__ A, const float* __restrict__ W,
    const float* __restrict__ bvec, float* __restrict__ C, int act,
    int m0, int n0)
{
    __shared__ __align__(16) float As[32][64];
    __shared__ __align__(16) float Ws[32][64];
    const int tid = threadIdx.x;
    const int row = tid & 63;          // 0..63
    const int kq  = (tid >> 6) * 8;    // 0,8,16,24
    const int tx = tid & 15, ty = tid >> 4;

    const float* ap = A + (size_t)(m0 + row) * CS + kq;
    const float* wp = W + (size_t)(n0 + row) * CS + kq;

    ull acc[4][2];
#pragma unroll
    for (int i = 0; i < 4; i++) { acc[i][0] = 0ULL; acc[i][1] = 0ULL; }

    float4 a0 = *(const float4*)ap;
    float4 a1 = *(const float4*)(ap + 4);
    float4 w0 = *(const float4*)wp;
    float4 w1 = *(const float4*)(wp + 4);

    for (int kt = 0; kt < CS / 32; kt++) {
        As[kq+0][row]=a0.x; As[kq+1][row]=a0.y; As[kq+2][row]=a0.z; As[kq+3][row]=a0.w;
        As[kq+4][row]=a1.x; As[kq+5][row]=a1.y; As[kq+6][row]=a1.z; As[kq+7][row]=a1.w;
        Ws[kq+0][row]=w0.x; Ws[kq+1][row]=w0.y; Ws[kq+2][row]=w0.z; Ws[kq+3][row]=w0.w;
        Ws[kq+4][row]=w1.x; Ws[kq+5][row]=w1.y; Ws[kq+6][row]=w1.z; Ws[kq+7][row]=w1.w;
        __syncthreads();

        if (kt + 1 < CS / 32) {
            const int ko = (kt + 1) * 32;
            a0 = *(const float4*)(ap + ko);
            a1 = *(const float4*)(ap + ko + 4);
            w0 = *(const float4*)(wp + ko);
            w1 = *(const float4*)(wp + ko + 4);
        }

#pragma unroll
        for (int k = 0; k < 32; k++) {
            float4 av = *(const float4*)&As[k][ty*4];
            ulonglong2 bv = *(const ulonglong2*)&Ws[k][tx*4];
            fma2(acc[0][0], dup2(av.x), bv.x); fma2(acc[0][1], dup2(av.x), bv.y);
            fma2(acc[1][0], dup2(av.y), bv.x); fma2(acc[1][1], dup2(av.y), bv.y);
            fma2(acc[2][0], dup2(av.z), bv.x); fma2(acc[2][1], dup2(av.z), bv.y);
            fma2(acc[3][0], dup2(av.w), bv.x); fma2(acc[3][1], dup2(av.w), bv.y);
        }
        __syncthreads();
    }

    float bv4[4] = {0.f, 0.f, 0.f, 0.f};
    if (bvec) {
        float4 b = *(const float4*)&bvec[n0 + tx*4];
        bv4[0] = b.x; bv4[1] = b.y; bv4[2] = b.z; bv4[3] = b.w;
    }

#pragma unroll
    for (int r = 0; r < 4; r++) {
        float o0, o1, o2, o3;
        unpack2(acc[r][0], o0, o1);
        unpack2(acc[r][1], o2, o3);
        o0 += bv4[0]; o1 += bv4[1]; o2 += bv4[2]; o3 += bv4[3];
        if (act) {
            o0 = 1.f/(1.f+__expf(-o0)); o1 = 1.f/(1.f+__expf(-o1));
            o2 = 1.f/(1.f+__expf(-o2)); o3 = 1.f/(1.f+__expf(-o3));
        }
        *(float4*)&C[(size_t)(m0 + ty*4 + r)*CS + n0 + tx*4] =
            make_float4(o0, o1, o2, o3);
    }
}

// K1: q/k/v/g projections
__global__ void __launch_bounds__(256) qkvg_kernel(
    const float* __restrict__ s,  const float* __restrict__ kin,
    const float* __restrict__ Wq, const float* __restrict__ bq,
    const float* __restrict__ Wk, const float* __restrict__ Wv,
    const float* __restrict__ Wg)
{
    const float* A; const float* W; const float* bv = nullptr;
    float* C; int act = 0;
    switch (blockIdx.z) {
        case 0:  A = s;   W = Wq; bv = bq; C = g_q; break;
        case 1:  A = kin; W = Wk;          C = g_k; break;
        case 2:  A = kin; W = Wv;          C = g_v; break;
        default: A = s;   W = Wg;          C = g_g; act = 1; break;
    }
    gemm_block64(A, W, bv, C, act, blockIdx.y * 64, blockIdx.x * 64);
}

// K4: out = og @ Wo^T
__global__ void __launch_bounds__(256) outproj_kernel(
    const float* __restrict__ Wo, float* __restrict__ out)
{
    gemm_block64(g_og, Wo, nullptr, out, 0, blockIdx.y * 64, blockIdx.x * 64);
}

// K2: bias[b,h,i,j] = LayerNorm(z[b,i,j,:]) . Wz[h,:]
__global__ void __launch_bounds__(256) biasproj_kernel(
    const float* __restrict__ z,   const float* __restrict__ lng,
    const float* __restrict__ lnb, const float* __restrict__ Wz)
{
    __shared__ __align__(16) ull A2[128][8];   // {g_c*Wz[2h], g_c*Wz[2h+1]}
    __shared__ float Sf[16], Cf[16];
    const int tid = threadIdx.x;
    if (tid < 128) {
        float gc = lng[tid];
#pragma unroll
        for (int h2 = 0; h2 < 8; h2++)
            A2[tid][h2] = pack2(gc * Wz[(2*h2)*CZ + tid], gc * Wz[(2*h2+1)*CZ + tid]);
    } else if (tid < 144) {
        int hh = tid - 128;
        float S = 0.f, Cc = 0.f;
        for (int c = 0; c < CZ; c++) {
            float w = Wz[hh*CZ + c];
            S  = fmaf(lng[c], w, S);
            Cc = fmaf(lnb[c], w, Cc);
        }
        Sf[hh] = S; Cf[hh] = Cc;
    }
    __syncthreads();

    const int idx = blockIdx.x * 256 + tid;
    const int j = idx % NN;
    const int t = idx / NN;
    const int i = t % NN;
    const int b = t / NN;

    const float* zp = z + (size_t)idx * CZ;
    ull acc[8];
#pragma unroll
    for (int h2 = 0; h2 < 8; h2++) acc[h2] = 0ULL;
    float sum = 0.f, sumsq = 0.f;

#pragma unroll 4
    for (int c4 = 0; c4 < CZ/4; c4++) {
        float4 zv = *(const float4*)(zp + c4*4);
        float zz[4] = {zv.x, zv.y, zv.z, zv.w};
#pragma unroll
        for (int u = 0; u < 4; u++) {
            const int c = c4*4 + u;
            float zc = zz[u];
            sum += zc;
            sumsq = fmaf(zc, zc, sumsq);
            ull zd = dup2(zc);
            const ulonglong2* ap = (const ulonglong2*)&A2[c][0];
            ulonglong2 a01 = ap[0], a23 = ap[1], a45 = ap[2], a67 = ap[3];
            fma2(acc[0], zd, a01.x); fma2(acc[1], zd, a01.y);
            fma2(acc[2], zd, a23.x); fma2(acc[3], zd, a23.y);
            fma2(acc[4], zd, a45.x); fma2(acc[5], zd, a45.y);
            fma2(acc[6], zd, a67.x); fma2(acc[7], zd, a67.y);
        }
    }

    const float inv = 1.f / CZ;
    float mu   = sum * inv;
    float var  = sumsq * inv - mu*mu;
    float rstd = rsqrtf(var + 1e-5f);

    const size_t base = ((size_t)b*HH*NN + i) * NN + j;
    const size_t hs   = (size_t)NN * NN;
#pragma unroll
    for (int h2 = 0; h2 < 8; h2++) {
        float d0, d1; unpack2(acc[h2], d0, d1);
        g_bias[base + (size_t)(2*h2)  *hs] = rstd*(d0 - mu*Sf[2*h2])   + Cf[2*h2];
        g_bias[base + (size_t)(2*h2+1)*hs] = rstd*(d1 - mu*Sf[2*h2+1]) + Cf[2*h2+1];
    }
}

__device__ __forceinline__ float shfl_max16(float v) {
    v = fmaxf(v, __shfl_xor_sync(0xffffffffu, v, 8));
    v = fmaxf(v, __shfl_xor_sync(0xffffffffu, v, 4));
    v = fmaxf(v, __shfl_xor_sync(0xffffffffu, v, 2));
    v = fmaxf(v, __shfl_xor_sync(0xffffffffu, v, 1));
    return v;
}
__device__ __forceinline__ float shfl_sum16(float v) {
    v += __shfl_xor_sync(0xffffffffu, v, 8);
    v += __shfl_xor_sync(0xffffffffu, v, 4);
    v += __shfl_xor_sync(0xffffffffu, v, 2);
    v += __shfl_xor_sync(0xffffffffu, v, 1);
    return v;
}

// K3: flash attention with pair bias + mask + gating (scores never hit HBM).
// Block = one (b,h,i-tile of 64 rows). Streams 64-wide j tiles; online softmax.
// S-phase: 16x16 threads, 4x4 each. P stored TRANSPOSED (ps_T[k][row]).
// PV-phase: 192 threads, 4 rows x 4 cols each; 2 LDS.128 per 8 FFMA2.
__global__ void __launch_bounds__(256, 3) attn_kernel(const float* __restrict__ mask)
{
    extern __shared__ float sm[];
    float* qs = sm;                   // [48][64]  qs[d*IT + i]
    float* ks = qs + 48*IT;           // [48][64]  ks[d*JT + j]
    float* vs = ks + 48*JT;           // [64][48]  vs[j*48 + d]
    float* pT = vs + JT*48;           // [64][PST] pT[k*PST + row]
    float* scale_s = pT + JT*PST;     // [64]
    float* l_s = scale_s + IT;        // [64]

    const int tid = threadIdx.x;
    const int h  = blockIdx.y & (HH-1);
    const int b  = blockIdx.y >> 4;
    const int i0 = blockIdx.x * IT;
    const int tx = tid & 15, ty = tid >> 4;   // S layout: 4 rows x 4 cols
    const int px = tid >> 4, py = tid & 15;   // PV layout (tid<192): 4r x 4c

    // load q tile transposed (once)
    for (int idx = tid; idx < IT * (HD/4); idx += 256) {
        const int r = idx / (HD/4), dq = idx % (HD/4);
        float4 v = *(const float4*)&g_q[((size_t)(b*NN + i0 + r))*CS + h*HD + dq*4];
        qs[(dq*4+0)*IT + r] = v.x; qs[(dq*4+1)*IT + r] = v.y;
        qs[(dq*4+2)*IT + r] = v.z; qs[(dq*4+3)*IT + r] = v.w;
    }

    float mrow[4] = {-1e30f, -1e30f, -1e30f, -1e30f};
    float lrow[4] = {0.f, 0.f, 0.f, 0.f};
    ull oacc[4][2];
#pragma unroll
    for (int r = 0; r < 4; r++) { oacc[r][0] = 0ULL; oacc[r][1] = 0ULL; }

    const size_t bh = ((size_t)b*HH + h) * (size_t)NN * NN;
    const float scale = 0.14433756729740643f;   // 1/sqrt(48)

    for (int jt = 0; jt < NN / JT; jt++) {
        const int j0 = jt * JT;
        __syncthreads();   // prev PV done with pT/vs

        // load k tile (transposed) + v tile
        for (int idx = tid; idx < JT * (HD/4); idx += 256) {
            const int j = idx / (HD/4), dq = idx % (HD/4);
            const size_t go = ((size_t)(b*NN + j0 + j))*CS + h*HD + dq*4;
            float4 kv = *(const float4*)&g_k[go];
            ks[(dq*4+0)*JT + j] = kv.x; ks[(dq*4+1)*JT + j] = kv.y;
            ks[(dq*4+2)*JT + j] = kv.z; ks[(dq*4+3)*JT + j] = kv.w;
            float4 vv = *(const float4*)&g_v[go];
            *(float4*)&vs[j*48 + dq*4] = vv;
        }
        __syncthreads();

        // ---- S phase: 4 rows x 4 cols per thread ----
        ull acc[4][2];
#pragma unroll
        for (int i = 0; i < 4; i++) { acc[i][0] = 0ULL; acc[i][1] = 0ULL; }

#pragma unroll 4
        for (int d = 0; d < HD; d++) {
            float4 a = *(const float4*)&qs[d*IT + ty*4];
            ulonglong2 kb = *(const ulonglong2*)&ks[d*JT + tx*4];
            fma2(acc[0][0], dup2(a.x), kb.x); fma2(acc[0][1], dup2(a.x), kb.y);
            fma2(acc[1][0], dup2(a.y), kb.x); fma2(acc[1][1], dup2(a.y), kb.y);
            fma2(acc[2][0], dup2(a.z), kb.x); fma2(acc[2][1], dup2(a.z), kb.y);
            fma2(acc[3][0], dup2(a.w), kb.x); fma2(acc[3][1], dup2(a.w), kb.y);
        }

        float4 mk = *(const float4*)&mask[b*NN + j0 + tx*4];
        float madd[4] = {(1.f-mk.x)*(-1e6f), (1.f-mk.y)*(-1e6f),
                         (1.f-mk.z)*(-1e6f), (1.f-mk.w)*(-1e6f)};

        float pr[4][4];
#pragma unroll
        for (int i = 0; i < 4; i++) {
            const int row = ty*4 + i;
            float sv[4];
            unpack2(acc[i][0], sv[0], sv[1]);
            unpack2(acc[i][1], sv[2], sv[3]);
            float4 bb = *(const float4*)&g_bias[bh + (size_t)(i0+row)*NN + j0 + tx*4];
            sv[0] = fmaf(sv[0], scale, bb.x + madd[0]);
            sv[1] = fmaf(sv[1], scale, bb.y + madd[1]);
            sv[2] = fmaf(sv[2], scale, bb.z + madd[2]);
            sv[3] = fmaf(sv[3], scale, bb.w + madd[3]);

            float rm = fmaxf(fmaxf(sv[0], sv[1]), fmaxf(sv[2], sv[3]));
            rm = shfl_max16(rm);
            float mn = fmaxf(mrow[i], rm);
            float p0 = __expf(sv[0] - mn), p1 = __expf(sv[1] - mn);
            float p2 = __expf(sv[2] - mn), p3 = __expf(sv[3] - mn);
            float rs = shfl_sum16(p0 + p1 + p2 + p3);
            float sc = __expf(mrow[i] - mn);
            lrow[i] = lrow[i] * sc + rs;
            mrow[i] = mn;
            pr[i][0] = p0; pr[i][1] = p1; pr[i][2] = p2; pr[i][3] = p3;
            if (tx == 0) scale_s[row] = sc;
        }
        // store P transposed: pT[col][4 rows]
#pragma unroll
        for (int c = 0; c < 4; c++) {
            *(float4*)&pT[(tx*4+c)*PST + ty*4] =
                make_float4(pr[0][c], pr[1][c], pr[2][c], pr[3][c]);
        }
        __syncthreads();

        // ---- PV phase: 192 threads, 4 rows x 4 cols each ----
        if (tid < 192) {
#pragma unroll
            for (int r = 0; r < 4; r++) {
                ull d = dup2(scale_s[py*4 + r]);
                mul2(oacc[r][0], d); mul2(oacc[r][1], d);
            }
            const float* pp = pT + py*4;
            const float* vp = vs + px*4;
#pragma unroll 4
            for (int k = 0; k < JT; k++) {
                float4 pv = *(const float4*)(pp + k*PST);
                ulonglong2 vv = *(const ulonglong2*)(vp + k*48);
                fma2(oacc[0][0], dup2(pv.x), vv.x); fma2(oacc[0][1], dup2(pv.x), vv.y);
                fma2(oacc[1][0], dup2(pv.y), vv.x); fma2(oacc[1][1], dup2(pv.y), vv.y);
                fma2(oacc[2][0], dup2(pv.z), vv.x); fma2(oacc[2][1], dup2(pv.z), vv.y);
                fma2(oacc[3][0], dup2(pv.w), vv.x); fma2(oacc[3][1], dup2(pv.w), vv.y);
            }
        }
    }

    // publish l
    if (tx == 0) {
#pragma unroll
        for (int i = 0; i < 4; i++) l_s[ty*4 + i] = lrow[i];
    }
    __syncthreads();

    // epilogue: divide by l, gate, store
    if (tid < 192) {
#pragma unroll
        for (int r = 0; r < 4; r++) {
            const int row = py*4 + r;
            const float inv = 1.f / l_s[row];
            const size_t off = ((size_t)(b*NN + i0 + row))*CS + h*HD + px*4;
            float o0, o1, o2, o3;
            unpack2(oacc[r][0], o0, o1);
            unpack2(oacc[r][1], o2, o3);
            float4 gg = *(const float4*)&g_g[off];
            *(float4*)&g_og[off] = make_float4(o0*inv*gg.x, o1*inv*gg.y,
                                               o2*inv*gg.z, o3*inv*gg.w);
        }
    }
}

extern "C" void kernel_launch(void* const* d_in, const int* in_sizes, int n_in,
                              void* d_out, int out_size)
{
    const float* s    = (const float*)d_in[0];
    const float* z    = (const float*)d_in[1];
    const float* mask = (const float*)d_in[2];
    const float* kin  = (const float*)d_in[3];
    const float* Wq   = (const float*)d_in[4];
    const float* bq   = (const float*)d_in[5];
    const float* Wk   = (const float*)d_in[6];
    const float* Wv   = (const float*)d_in[7];
    const float* Wg   = (const float*)d_in[8];
    const float* lng  = (const float*)d_in[9];
    const float* lnb  = (const float*)d_in[10];
    const float* Wz   = (const float*)d_in[11];
    const float* Wo   = (const float*)d_in[12];
    float* out = (float*)d_out;

    const int attn_smem = (48*IT + 48*JT + JT*48 + JT*PST + IT + IT) * 4;
    cudaFuncSetAttribute(attn_kernel,
                         cudaFuncAttributeMaxDynamicSharedMemorySize, attn_smem);

    qkvg_kernel<<<dim3(CS/64, BB*NN/64, 4), 256>>>(s, kin, Wq, bq, Wk, Wv, Wg);
    biasproj_kernel<<<BB*NN*NN/256, 256>>>(z, lng, lnb, Wz);
    attn_kernel<<<dim3(NN/IT, BB*HH), 256, attn_smem>>>(mask);
    outproj_kernel<<<dim3(CS/64, BB*NN/64), 256>>>(Wo, out);
}

// round 9
// speedup vs baseline: 1.1565x; 1.1565x over previous
#include <cuda_runtime.h>
#include <cstdint>

typedef unsigned long long ull;

#define BB 2
#define NN 768
#define CS 768
#define HH 16
#define HD 48
#define CZ 128

#define IT 64      // attention i-tile rows
#define JT 64      // attention j-tile cols
#define PSS 68     // P tile row stride (pad for banks, keeps 8B align)

// ----- scratch (static device globals: no allocation allowed) -----
__device__ float g_q [BB*NN*CS];
__device__ float g_k [BB*NN*CS];
__device__ float g_v [BB*NN*CS];
__device__ float g_g [BB*NN*CS];
__device__ float g_og[BB*NN*CS];
__device__ float g_bias[(size_t)BB*HH*NN*NN];

// ----- packed f32x2 helpers -----
__device__ __forceinline__ ull pack2(float x, float y) {
    ull r; asm("mov.b64 %0, {%1, %2};" : "=l"(r) : "f"(x), "f"(y)); return r;
}
__device__ __forceinline__ ull dup2(float x) { return pack2(x, x); }
__device__ __forceinline__ void fma2(ull& d, ull a, ull b) {
    asm("fma.rn.f32x2 %0, %1, %2, %0;" : "+l"(d) : "l"(a), "l"(b));
}
__device__ __forceinline__ void mul2(ull& d, ull a) {
    asm("mul.rn.f32x2 %0, %0, %1;" : "+l"(d) : "l"(a));
}
__device__ __forceinline__ void unpack2(ull v, float& x, float& y) {
    asm("mov.b64 {%0, %1}, %2;" : "=f"(x), "=f"(y) : "l"(v));
}

// ----- 128x128 tiled GEMM, BK=16, 256 threads, 8x8/thread (BALANCED:
// 32 FFMA2 per 4 LDS.128 per thread per k). Optional K-range for split-K. ----
__device__ __forceinline__ void gemm_block(
    const float* __restrict__ A, const float* __restrict__ W,
    const float* __restrict__ bvec, float* __restrict__ C, int act,
    int m0, int n0, int kbeg, int ktiles)
{
    __shared__ __align__(16) float As[16][128];
    __shared__ __align__(16) float Ws[16][128];
    const int tid = threadIdx.x;
    const int lr = tid >> 1;
    const int lq = (tid & 1) * 8;
    const int tx = tid & 15, ty = tid >> 4;

    const float* ap = A + (size_t)(m0 + lr) * CS + kbeg + lq;
    const float* wp = W + (size_t)(n0 + lr) * CS + kbeg + lq;

    ull acc[8][4];
#pragma unroll
    for (int i = 0; i < 8; i++)
#pragma unroll
        for (int j = 0; j < 4; j++) acc[i][j] = 0ULL;

    float4 a0 = *(const float4*)ap;
    float4 a1 = *(const float4*)(ap + 4);
    float4 w0 = *(const float4*)wp;
    float4 w1 = *(const float4*)(wp + 4);

    for (int kt = 0; kt < ktiles; kt++) {
        As[lq+0][lr]=a0.x; As[lq+1][lr]=a0.y; As[lq+2][lr]=a0.z; As[lq+3][lr]=a0.w;
        As[lq+4][lr]=a1.x; As[lq+5][lr]=a1.y; As[lq+6][lr]=a1.z; As[lq+7][lr]=a1.w;
        Ws[lq+0][lr]=w0.x; Ws[lq+1][lr]=w0.y; Ws[lq+2][lr]=w0.z; Ws[lq+3][lr]=w0.w;
        Ws[lq+4][lr]=w1.x; Ws[lq+5][lr]=w1.y; Ws[lq+6][lr]=w1.z; Ws[lq+7][lr]=w1.w;
        __syncthreads();

        if (kt + 1 < ktiles) {                  // prefetch next k-tile
            const int ko = (kt + 1) * 16;
            a0 = *(const float4*)(ap + ko);
            a1 = *(const float4*)(ap + ko + 4);
            w0 = *(const float4*)(wp + ko);
            w1 = *(const float4*)(wp + ko + 4);
        }

#pragma unroll
        for (int k = 0; k < 16; k++) {
            float4 fa0 = *(const float4*)&As[k][ty*8];
            float4 fa1 = *(const float4*)&As[k][ty*8+4];
            ulonglong2 b01 = *(const ulonglong2*)&Ws[k][tx*8];
            ulonglong2 b23 = *(const ulonglong2*)&Ws[k][tx*8+4];
            float av[8] = {fa0.x,fa0.y,fa0.z,fa0.w,fa1.x,fa1.y,fa1.z,fa1.w};
#pragma unroll
            for (int i = 0; i < 8; i++) {
                ull ad = dup2(av[i]);
                fma2(acc[i][0], ad, b01.x);
                fma2(acc[i][1], ad, b01.y);
                fma2(acc[i][2], ad, b23.x);
                fma2(acc[i][3], ad, b23.y);
            }
        }
        __syncthreads();
    }

    float bv[8];
    if (bvec) {
        float4 b0 = *(const float4*)&bvec[n0 + tx*8];
        float4 b1 = *(const float4*)&bvec[n0 + tx*8 + 4];
        bv[0]=b0.x; bv[1]=b0.y; bv[2]=b0.z; bv[3]=b0.w;
        bv[4]=b1.x; bv[5]=b1.y; bv[6]=b1.z; bv[7]=b1.w;
    } else {
#pragma unroll
        for (int c = 0; c < 8; c++) bv[c] = 0.f;
    }

#pragma unroll
    for (int i = 0; i < 8; i++) {
        float r[8];
#pragma unroll
        for (int j = 0; j < 4; j++) unpack2(acc[i][j], r[2*j], r[2*j+1]);
#pragma unroll
        for (int c = 0; c < 8; c++) {
            r[c] += bv[c];
            if (act) r[c] = 1.f / (1.f + __expf(-r[c]));
        }
        float* cp = C + (size_t)(m0 + ty*8 + i) * CS + n0 + tx*8;
        *(float4*)cp     = make_float4(r[0], r[1], r[2], r[3]);
        *(float4*)(cp+4) = make_float4(r[4], r[5], r[6], r[7]);
    }
}

// K1: q/k/v/g projections
__global__ void __launch_bounds__(256) qkvg_kernel(
    const float* __restrict__ s,  const float* __restrict__ kin,
    const float* __restrict__ Wq, const float* __restrict__ bq,
    const float* __restrict__ Wk, const float* __restrict__ Wv,
    const float* __restrict__ Wg)
{
    const float* A; const float* W; const float* bv = nullptr;
    float* C; int act = 0;
    switch (blockIdx.z) {
        case 0:  A = s;   W = Wq; bv = bq; C = g_q; break;
        case 1:  A = kin; W = Wk;          C = g_k; break;
        case 2:  A = kin; W = Wv;          C = g_v; break;
        default: A = s;   W = Wg;          C = g_g; act = 1; break;
    }
    gemm_block(A, W, bv, C, act, blockIdx.y * 128, blockIdx.x * 128, 0, CS/16);
}

// K4: out partials = og @ Wo^T over K-quarter. Partials land in the dead
// q/k/v/g scratch buffers (free after attn).
__global__ void __launch_bounds__(256) outproj_partial_kernel(
    const float* __restrict__ Wo)
{
    float* part;
    switch (blockIdx.z) {
        case 0:  part = g_q; break;
        case 1:  part = g_k; break;
        case 2:  part = g_v; break;
        default: part = g_g; break;
    }
    gemm_block(g_og, Wo, nullptr, part, 0,
               blockIdx.y * 128, blockIdx.x * 128,
               blockIdx.z * (CS/4), (CS/4)/16);
}

// K5: out = p0+p1+p2+p3
__global__ void __launch_bounds__(256) reduce4_kernel(float* __restrict__ out)
{
    const int i = blockIdx.x * 256 + threadIdx.x;
    float4 a = ((const float4*)g_q)[i];
    float4 b = ((const float4*)g_k)[i];
    float4 c = ((const float4*)g_v)[i];
    float4 d = ((const float4*)g_g)[i];
    ((float4*)out)[i] = make_float4(a.x+b.x+c.x+d.x, a.y+b.y+c.y+d.y,
                                    a.z+b.z+c.z+d.z, a.w+b.w+c.w+d.w);
}

// K2: bias[b,h,i,j] = LayerNorm(z[b,i,j,:]) . Wz[h,:]
__global__ void __launch_bounds__(256) biasproj_kernel(
    const float* __restrict__ z,   const float* __restrict__ lng,
    const float* __restrict__ lnb, const float* __restrict__ Wz)
{
    __shared__ __align__(16) ull A2[128][8];   // {g_c*Wz[2h], g_c*Wz[2h+1]}
    __shared__ float Sf[16], Cf[16];
    const int tid = threadIdx.x;
    if (tid < 128) {
        float gc = lng[tid];
#pragma unroll
        for (int h2 = 0; h2 < 8; h2++)
            A2[tid][h2] = pack2(gc * Wz[(2*h2)*CZ + tid], gc * Wz[(2*h2+1)*CZ + tid]);
    } else if (tid < 144) {
        int hh = tid - 128;
        float S = 0.f, Cc = 0.f;
        for (int c = 0; c < CZ; c++) {
            float w = Wz[hh*CZ + c];
            S  = fmaf(lng[c], w, S);
            Cc = fmaf(lnb[c], w, Cc);
        }
        Sf[hh] = S; Cf[hh] = Cc;
    }
    __syncthreads();

    const int idx = blockIdx.x * 256 + tid;
    const int j = idx % NN;
    const int t = idx / NN;
    const int i = t % NN;
    const int b = t / NN;

    const float* zp = z + (size_t)idx * CZ;
    ull acc[8];
#pragma unroll
    for (int h2 = 0; h2 < 8; h2++) acc[h2] = 0ULL;
    float sum = 0.f, sumsq = 0.f;

#pragma unroll 4
    for (int c4 = 0; c4 < CZ/4; c4++) {
        float4 zv = *(const float4*)(zp + c4*4);
        float zz[4] = {zv.x, zv.y, zv.z, zv.w};
#pragma unroll
        for (int u = 0; u < 4; u++) {
            const int c = c4*4 + u;
            float zc = zz[u];
            sum += zc;
            sumsq = fmaf(zc, zc, sumsq);
            ull zd = dup2(zc);
            const ulonglong2* ap = (const ulonglong2*)&A2[c][0];
            ulonglong2 a01 = ap[0], a23 = ap[1], a45 = ap[2], a67 = ap[3];
            fma2(acc[0], zd, a01.x); fma2(acc[1], zd, a01.y);
            fma2(acc[2], zd, a23.x); fma2(acc[3], zd, a23.y);
            fma2(acc[4], zd, a45.x); fma2(acc[5], zd, a45.y);
            fma2(acc[6], zd, a67.x); fma2(acc[7], zd, a67.y);
        }
    }

    const float inv = 1.f / CZ;
    float mu   = sum * inv;
    float var  = sumsq * inv - mu*mu;
    float rstd = rsqrtf(var + 1e-5f);

    const size_t base = ((size_t)b*HH*NN + i) * NN + j;
    const size_t hs   = (size_t)NN * NN;
#pragma unroll
    for (int h2 = 0; h2 < 8; h2++) {
        float d0, d1; unpack2(acc[h2], d0, d1);
        g_bias[base + (size_t)(2*h2)  *hs] = rstd*(d0 - mu*Sf[2*h2])   + Cf[2*h2];
        g_bias[base + (size_t)(2*h2+1)*hs] = rstd*(d1 - mu*Sf[2*h2+1]) + Cf[2*h2+1];
    }
}

__device__ __forceinline__ float shfl_max16(float v) {
    v = fmaxf(v, __shfl_xor_sync(0xffffffffu, v, 8));
    v = fmaxf(v, __shfl_xor_sync(0xffffffffu, v, 4));
    v = fmaxf(v, __shfl_xor_sync(0xffffffffu, v, 2));
    v = fmaxf(v, __shfl_xor_sync(0xffffffffu, v, 1));
    return v;
}
__device__ __forceinline__ float shfl_sum16(float v) {
    v += __shfl_xor_sync(0xffffffffu, v, 8);
    v += __shfl_xor_sync(0xffffffffu, v, 4);
    v += __shfl_xor_sync(0xffffffffu, v, 2);
    v += __shfl_xor_sync(0xffffffffu, v, 1);
    return v;
}

// K3: flash attention with pair bias + mask + gating (scores never hit HBM).
// Block = one (b,h,i-tile of 64 rows). Streams 64-wide j tiles; online softmax.
__global__ void __launch_bounds__(256) attn_kernel(const float* __restrict__ mask)
{
    extern __shared__ float sm[];
    float* qs = sm;                       // [48][64]  qs[d*IT + i]
    float* ks = sm + 48*IT;               // [48][64]  ks[d*JT + j]
    float* vs = ks + 48*JT;               // [64][48]  vs[j*48 + d]
    float* ps = vs + JT*48;               // [64][PSS]
    float* scale_s = ps + IT*PSS;         // [64]
    float* l_s = scale_s + IT;            // [64]

    const int tid = threadIdx.x;
    const int h  = blockIdx.y & (HH-1);
    const int b  = blockIdx.y >> 4;
    const int i0 = blockIdx.x * IT;
    const int tx = tid & 15, ty = tid >> 4;   // S layout: 4 rows x 4 cols
    const int tx2 = tid & 7, ty2 = tid >> 3;  // PV layout: 2 rows x 6 cols

    // load q tile transposed (once)
    for (int idx = tid; idx < IT * (HD/4); idx += 256) {
        const int r = idx / (HD/4), dq = idx % (HD/4);
        float4 v = *(const float4*)&g_q[((size_t)(b*NN + i0 + r))*CS + h*HD + dq*4];
        qs[(dq*4+0)*IT + r] = v.x; qs[(dq*4+1)*IT + r] = v.y;
        qs[(dq*4+2)*IT + r] = v.z; qs[(dq*4+3)*IT + r] = v.w;
    }

    float mrow[4] = {-1e30f, -1e30f, -1e30f, -1e30f};
    float lrow[4] = {0.f, 0.f, 0.f, 0.f};
    ull oacc[2][3];
#pragma unroll
    for (int r = 0; r < 2; r++)
#pragma unroll
        for (int c = 0; c < 3; c++) oacc[r][c] = 0ULL;

    const size_t bh = ((size_t)b*HH + h) * (size_t)NN * NN;
    const float scale = 0.14433756729740643f;   // 1/sqrt(48)

    for (int jt = 0; jt < NN / JT; jt++) {
        const int j0 = jt * JT;
        __syncthreads();   // prev PV done with ps/vs

        // load k tile (transposed) + v tile
        for (int idx = tid; idx < JT * (HD/4); idx += 256) {
            const int j = idx / (HD/4), dq = idx % (HD/4);
            const size_t go = ((size_t)(b*NN + j0 + j))*CS + h*HD + dq*4;
            float4 kv = *(const float4*)&g_k[go];
            ks[(dq*4+0)*JT + j] = kv.x; ks[(dq*4+1)*JT + j] = kv.y;
            ks[(dq*4+2)*JT + j] = kv.z; ks[(dq*4+3)*JT + j] = kv.w;
            float4 vv = *(const float4*)&g_v[go];
            *(float4*)&vs[j*48 + dq*4] = vv;
        }
        __syncthreads();

        // ---- S phase: 4 rows x 4 cols per thread ----
        ull acc[4][2];
#pragma unroll
        for (int i = 0; i < 4; i++) { acc[i][0] = 0ULL; acc[i][1] = 0ULL; }

#pragma unroll 4
        for (int d = 0; d < HD; d++) {
            float4 a = *(const float4*)&qs[d*IT + ty*4];
            ulonglong2 kb = *(const ulonglong2*)&ks[d*JT + tx*4];
            float av[4] = {a.x, a.y, a.z, a.w};
#pragma unroll
            for (int i = 0; i < 4; i++) {
                ull ad = dup2(av[i]);
                fma2(acc[i][0], ad, kb.x);
                fma2(acc[i][1], ad, kb.y);
            }
        }

        float4 mk = *(const float4*)&mask[b*NN + j0 + tx*4];
        float madd[4] = {(1.f-mk.x)*(-1e6f), (1.f-mk.y)*(-1e6f),
                         (1.f-mk.z)*(-1e6f), (1.f-mk.w)*(-1e6f)};

#pragma unroll
        for (int i = 0; i < 4; i++) {
            const int row = ty*4 + i;
            float sv[4];
            unpack2(acc[i][0], sv[0], sv[1]);
            unpack2(acc[i][1], sv[2], sv[3]);
            float4 bb = *(const float4*)&g_bias[bh + (size_t)(i0+row)*NN + j0 + tx*4];
            sv[0] = fmaf(sv[0], scale, bb.x + madd[0]);
            sv[1] = fmaf(sv[1], scale, bb.y + madd[1]);
            sv[2] = fmaf(sv[2], scale, bb.z + madd[2]);
            sv[3] = fmaf(sv[3], scale, bb.w + madd[3]);

            float rm = fmaxf(fmaxf(sv[0], sv[1]), fmaxf(sv[2], sv[3]));
            rm = shfl_max16(rm);
            float mn = fmaxf(mrow[i], rm);
            float p0 = __expf(sv[0] - mn), p1 = __expf(sv[1] - mn);
            float p2 = __expf(sv[2] - mn), p3 = __expf(sv[3] - mn);
            float rs = shfl_sum16(p0 + p1 + p2 + p3);
            float sc = __expf(mrow[i] - mn);
            lrow[i] = lrow[i] * sc + rs;
            mrow[i] = mn;
            *(float4*)&ps[row*PSS + tx*4] = make_float4(p0, p1, p2, p3);
            if (tx == 0) scale_s[row] = sc;
        }
        __syncthreads();

        // ---- PV phase: 2 rows x 6 cols per thread ----
        {
            const int r0 = ty2*2, r1 = ty2*2 + 1;
            ull d0 = dup2(scale_s[r0]);
            ull d1 = dup2(scale_s[r1]);
#pragma unroll
            for (int c = 0; c < 3; c++) { mul2(oacc[0][c], d0); mul2(oacc[1][c], d1); }

            const float* vbase = vs + tx2*6;
#pragma unroll 4
            for (int k = 0; k < JT; k += 2) {
                ull pk0 = *(const ull*)&ps[r0*PSS + k];
                ull pk1 = *(const ull*)&ps[r1*PSS + k];
                float p00, p01, p10, p11;
                unpack2(pk0, p00, p01);
                unpack2(pk1, p10, p11);
                const float* v0 = vbase + k*48;
                const float* v1 = v0 + 48;
                ull va0 = *(const ull*)(v0);
                ull va1 = *(const ull*)(v0 + 2);
                ull va2 = *(const ull*)(v0 + 4);
                ull vb0 = *(const ull*)(v1);
                ull vb1 = *(const ull*)(v1 + 2);
                ull vb2 = *(const ull*)(v1 + 4);
                ull a00 = dup2(p00), a10 = dup2(p10);
                fma2(oacc[0][0], a00, va0); fma2(oacc[0][1], a00, va1); fma2(oacc[0][2], a00, va2);
                fma2(oacc[1][0], a10, va0); fma2(oacc[1][1], a10, va1); fma2(oacc[1][2], a10, va2);
                ull a01 = dup2(p01), a11 = dup2(p11);
                fma2(oacc[0][0], a01, vb0); fma2(oacc[0][1], a01, vb1); fma2(oacc[0][2], a01, vb2);
                fma2(oacc[1][0], a11, vb0); fma2(oacc[1][1], a11, vb1); fma2(oacc[1][2], a11, vb2);
            }
        }
    }

    // publish l for PV-layout threads
    if (tx == 0) {
#pragma unroll
        for (int i = 0; i < 4; i++) l_s[ty*4 + i] = lrow[i];
    }
    __syncthreads();

    // epilogue: divide by l, gate, store
#pragma unroll
    for (int r = 0; r < 2; r++) {
        const int row = ty2*2 + r;
        const float inv = 1.f / l_s[row];
        const size_t off = ((size_t)(b*NN + i0 + row))*CS + h*HD + tx2*6;
#pragma unroll
        for (int c = 0; c < 3; c++) {
            float o0, o1;
            unpack2(oacc[r][c], o0, o1);
            float gg0 = g_g[off + 2*c], gg1 = g_g[off + 2*c + 1];
            *(ull*)&g_og[off + 2*c] = pack2(o0 * inv * gg0, o1 * inv * gg1);
        }
    }
}

extern "C" void kernel_launch(void* const* d_in, const int* in_sizes, int n_in,
                              void* d_out, int out_size)
{
    const float* s    = (const float*)d_in[0];
    const float* z    = (const float*)d_in[1];
    const float* mask = (const float*)d_in[2];
    const float* kin  = (const float*)d_in[3];
    const float* Wq   = (const float*)d_in[4];
    const float* bq   = (const float*)d_in[5];
    const float* Wk   = (const float*)d_in[6];
    const float* Wv   = (const float*)d_in[7];
    const float* Wg   = (const float*)d_in[8];
    const float* lng  = (const float*)d_in[9];
    const float* lnb  = (const float*)d_in[10];
    const float* Wz   = (const float*)d_in[11];
    const float* Wo   = (const float*)d_in[12];
    float* out = (float*)d_out;

    const int attn_smem = (48*IT + 48*JT + JT*48 + IT*PSS + IT + IT) * 4;
    cudaFuncSetAttribute(attn_kernel,
                         cudaFuncAttributeMaxDynamicSharedMemorySize, attn_smem);

    qkvg_kernel<<<dim3(CS/128, BB*NN/128, 4), 256>>>(s, kin, Wq, bq, Wk, Wv, Wg);
    biasproj_kernel<<<BB*NN*NN/256, 256>>>(z, lng, lnb, Wz);
    attn_kernel<<<dim3(NN/IT, BB*HH), 256, attn_smem>>>(mask);
    outproj_partial_kernel<<<dim3(CS/128, BB*NN/128, 4), 256>>>(Wo);
    reduce4_kernel<<<(BB*NN*CS/4)/256, 256>>>(out);
}

// round 10
// speedup vs baseline: 1.2941x; 1.1190x over previous
#include <cuda_runtime.h>
#include <cstdint>

typedef unsigned long long ull;

#define BB 2
#define NN 768
#define CS 768
#define HH 16
#define HD 48
#define CZ 128

#define IT 64      // attention i-tile rows
#define JT 64      // attention j-tile cols
#define PSS 68     // P tile row stride (pad for banks, keeps 8B align)

// ----- scratch (static device globals: no allocation allowed) -----
__device__ float g_q [BB*NN*CS];
__device__ float g_k [BB*NN*CS];
__device__ float g_v [BB*NN*CS];
__device__ float g_g [BB*NN*CS];
__device__ float g_og[BB*NN*CS];
__device__ float g_bias[(size_t)BB*HH*NN*NN];

// ----- packed f32x2 helpers -----
__device__ __forceinline__ ull pack2(float x, float y) {
    ull r; asm("mov.b64 %0, {%1, %2};" : "=l"(r) : "f"(x), "f"(y)); return r;
}
__device__ __forceinline__ ull dup2(float x) { return pack2(x, x); }
__device__ __forceinline__ void fma2(ull& d, ull a, ull b) {
    asm("fma.rn.f32x2 %0, %1, %2, %0;" : "+l"(d) : "l"(a), "l"(b));
}
__device__ __forceinline__ void mul2(ull& d, ull a) {
    asm("mul.rn.f32x2 %0, %0, %1;" : "+l"(d) : "l"(a));
}
__device__ __forceinline__ void unpack2(ull v, float& x, float& y) {
    asm("mov.b64 {%0, %1}, %2;" : "=f"(x), "=f"(y) : "l"(v));
}

// ----- 128x128 tiled GEMM, BK=16, 256 threads, 8x8/thread, DOUBLE-BUFFERED
// (one barrier per k-tile; LDG prefetch hidden under compute). Balanced:
// 32 FFMA2 per 4 LDS.128 per thread per k. Optional K-range for split-K. ----
__device__ __forceinline__ void gemm_block(
    const float* __restrict__ A, const float* __restrict__ W,
    const float* __restrict__ bvec, float* __restrict__ C, int act,
    int m0, int n0, int kbeg, int ktiles)
{
    __shared__ __align__(16) float As[2][16][128];
    __shared__ __align__(16) float Ws[2][16][128];
    const int tid = threadIdx.x;
    const int lr = tid >> 1;
    const int lq = (tid & 1) * 8;
    const int tx = tid & 15, ty = tid >> 4;

    const float* ap = A + (size_t)(m0 + lr) * CS + kbeg + lq;
    const float* wp = W + (size_t)(n0 + lr) * CS + kbeg + lq;

    ull acc[8][4];
#pragma unroll
    for (int i = 0; i < 8; i++)
#pragma unroll
        for (int j = 0; j < 4; j++) acc[i][j] = 0ULL;

    float4 a0 = *(const float4*)ap;
    float4 a1 = *(const float4*)(ap + 4);
    float4 w0 = *(const float4*)wp;
    float4 w1 = *(const float4*)(wp + 4);

    for (int kt = 0; kt < ktiles; kt++) {
        const int buf = kt & 1;
        As[buf][lq+0][lr]=a0.x; As[buf][lq+1][lr]=a0.y;
        As[buf][lq+2][lr]=a0.z; As[buf][lq+3][lr]=a0.w;
        As[buf][lq+4][lr]=a1.x; As[buf][lq+5][lr]=a1.y;
        As[buf][lq+6][lr]=a1.z; As[buf][lq+7][lr]=a1.w;
        Ws[buf][lq+0][lr]=w0.x; Ws[buf][lq+1][lr]=w0.y;
        Ws[buf][lq+2][lr]=w0.z; Ws[buf][lq+3][lr]=w0.w;
        Ws[buf][lq+4][lr]=w1.x; Ws[buf][lq+5][lr]=w1.y;
        Ws[buf][lq+6][lr]=w1.z; Ws[buf][lq+7][lr]=w1.w;
        __syncthreads();

        if (kt + 1 < ktiles) {                  // prefetch next k-tile
            const int ko = (kt + 1) * 16;
            a0 = *(const float4*)(ap + ko);
            a1 = *(const float4*)(ap + ko + 4);
            w0 = *(const float4*)(wp + ko);
            w1 = *(const float4*)(wp + ko + 4);
        }

#pragma unroll
        for (int k = 0; k < 16; k++) {
            float4 fa0 = *(const float4*)&As[buf][k][ty*8];
            float4 fa1 = *(const float4*)&As[buf][k][ty*8+4];
            ulonglong2 b01 = *(const ulonglong2*)&Ws[buf][k][tx*8];
            ulonglong2 b23 = *(const ulonglong2*)&Ws[buf][k][tx*8+4];
            float av[8] = {fa0.x,fa0.y,fa0.z,fa0.w,fa1.x,fa1.y,fa1.z,fa1.w};
#pragma unroll
            for (int i = 0; i < 8; i++) {
                ull ad = dup2(av[i]);
                fma2(acc[i][0], ad, b01.x);
                fma2(acc[i][1], ad, b01.y);
                fma2(acc[i][2], ad, b23.x);
                fma2(acc[i][3], ad, b23.y);
            }
        }
        // no trailing barrier: next STS targets the other buffer, and the
        // barrier above separates it from the prior compute on that buffer.
    }

    float bv[8];
    if (bvec) {
        float4 b0 = *(const float4*)&bvec[n0 + tx*8];
        float4 b1 = *(const float4*)&bvec[n0 + tx*8 + 4];
        bv[0]=b0.x; bv[1]=b0.y; bv[2]=b0.z; bv[3]=b0.w;
        bv[4]=b1.x; bv[5]=b1.y; bv[6]=b1.z; bv[7]=b1.w;
    } else {
#pragma unroll
        for (int c = 0; c < 8; c++) bv[c] = 0.f;
    }

#pragma unroll
    for (int i = 0; i < 8; i++) {
        float r[8];
#pragma unroll
        for (int j = 0; j < 4; j++) unpack2(acc[i][j], r[2*j], r[2*j+1]);
#pragma unroll
        for (int c = 0; c < 8; c++) {
            r[c] += bv[c];
            if (act) r[c] = 1.f / (1.f + __expf(-r[c]));
        }
        float* cp = C + (size_t)(m0 + ty*8 + i) * CS + n0 + tx*8;
        *(float4*)cp     = make_float4(r[0], r[1], r[2], r[3]);
        *(float4*)(cp+4) = make_float4(r[4], r[5], r[6], r[7]);
    }
}

// K1: q/k/v/g projections
__global__ void __launch_bounds__(256) qkvg_kernel(
    const float* __restrict__ s,  const float* __restrict__ kin,
    const float* __restrict__ Wq, const float* __restrict__ bq,
    const float* __restrict__ Wk, const float* __restrict__ Wv,
    const float* __restrict__ Wg)
{
    const float* A; const float* W; const float* bv = nullptr;
    float* C; int act = 0;
    switch (blockIdx.z) {
        case 0:  A = s;   W = Wq; bv = bq; C = g_q; break;
        case 1:  A = kin; W = Wk;          C = g_k; break;
        case 2:  A = kin; W = Wv;          C = g_v; break;
        default: A = s;   W = Wg;          C = g_g; act = 1; break;
    }
    gemm_block(A, W, bv, C, act, blockIdx.y * 128, blockIdx.x * 128, 0, CS/16);
}

// K4: out partials = og @ Wo^T over K-quarter, into dead q/k/v/g scratch.
__global__ void __launch_bounds__(256) outproj_partial_kernel(
    const float* __restrict__ Wo)
{
    float* part;
    switch (blockIdx.z) {
        case 0:  part = g_q; break;
        case 1:  part = g_k; break;
        case 2:  part = g_v; break;
        default: part = g_g; break;
    }
    gemm_block(g_og, Wo, nullptr, part, 0,
               blockIdx.y * 128, blockIdx.x * 128,
               blockIdx.z * (CS/4), (CS/4)/16);
}

// K5: out = p0+p1+p2+p3
__global__ void __launch_bounds__(256) reduce4_kernel(float* __restrict__ out)
{
    const int i = blockIdx.x * 256 + threadIdx.x;
    float4 a = ((const float4*)g_q)[i];
    float4 b = ((const float4*)g_k)[i];
    float4 c = ((const float4*)g_v)[i];
    float4 d = ((const float4*)g_g)[i];
    ((float4*)out)[i] = make_float4(a.x+b.x+c.x+d.x, a.y+b.y+c.y+d.y,
                                    a.z+b.z+c.z+d.z, a.w+b.w+c.w+d.w);
}

// K2: bias[b,h,i,j] = LayerNorm(z[b,i,j,:]) . Wz[h,:]
// COALESCED: z staged through smem in 256-row x 32-col tiles. Global loads
// are 128B/8-lane coalesced; compute reads own row from smem with 36-float
// padded stride (bank = 4t+c mod 32 -> conflict-free LDS.128 phases).
__global__ void __launch_bounds__(256) biasproj_kernel(
    const float* __restrict__ z,   const float* __restrict__ lng,
    const float* __restrict__ lnb, const float* __restrict__ Wz)
{
    __shared__ __align__(16) ull A2[128][8];   // {g_c*Wz[2h], g_c*Wz[2h+1]}
    __shared__ float Sf[16], Cf[16];
    __shared__ __align__(16) float zt[256][36];
    const int tid = threadIdx.x;
    if (tid < 128) {
        float gc = lng[tid];
#pragma unroll
        for (int h2 = 0; h2 < 8; h2++)
            A2[tid][h2] = pack2(gc * Wz[(2*h2)*CZ + tid], gc * Wz[(2*h2+1)*CZ + tid]);
    } else if (tid < 144) {
        int hh = tid - 128;
        float S = 0.f, Cc = 0.f;
        for (int c = 0; c < CZ; c++) {
            float w = Wz[hh*CZ + c];
            S  = fmaf(lng[c], w, S);
            Cc = fmaf(lnb[c], w, Cc);
        }
        Sf[hh] = S; Cf[hh] = Cc;
    }
    __syncthreads();

    const int row0 = blockIdx.x * 256;
    const int row  = row0 + tid;
    const int j = row % NN;
    const int t = row / NN;
    const int i = t % NN;
    const int b = t / NN;

    ull acc[8];
#pragma unroll
    for (int h2 = 0; h2 < 8; h2++) acc[h2] = 0ULL;
    float sum = 0.f, sumsq = 0.f;

    for (int ct = 0; ct < CZ/32; ct++) {
        // cooperative coalesced load: 256 rows x 32 floats
#pragma unroll
        for (int u = 0; u < 8; u++) {
            const int idx = u * 256 + tid;
            const int r = idx >> 3, q = idx & 7;
            *(float4*)&zt[r][q*4] =
                *(const float4*)&z[(size_t)(row0 + r)*CZ + ct*32 + q*4];
        }
        __syncthreads();

#pragma unroll
        for (int cq = 0; cq < 8; cq++) {
            float4 zv = *(const float4*)&zt[tid][cq*4];
            float zz[4] = {zv.x, zv.y, zv.z, zv.w};
#pragma unroll
            for (int u = 0; u < 4; u++) {
                const int c = ct*32 + cq*4 + u;
                float zc = zz[u];
                sum += zc;
                sumsq = fmaf(zc, zc, sumsq);
                ull zd = dup2(zc);
                const ulonglong2* ap = (const ulonglong2*)&A2[c][0];
                ulonglong2 a01 = ap[0], a23 = ap[1], a45 = ap[2], a67 = ap[3];
                fma2(acc[0], zd, a01.x); fma2(acc[1], zd, a01.y);
                fma2(acc[2], zd, a23.x); fma2(acc[3], zd, a23.y);
                fma2(acc[4], zd, a45.x); fma2(acc[5], zd, a45.y);
                fma2(acc[6], zd, a67.x); fma2(acc[7], zd, a67.y);
            }
        }
        __syncthreads();
    }

    const float inv = 1.f / CZ;
    float mu   = sum * inv;
    float var  = sumsq * inv - mu*mu;
    float rstd = rsqrtf(var + 1e-5f);

    const size_t base = ((size_t)b*HH*NN + i) * NN + j;
    const size_t hs   = (size_t)NN * NN;
#pragma unroll
    for (int h2 = 0; h2 < 8; h2++) {
        float d0, d1; unpack2(acc[h2], d0, d1);
        g_bias[base + (size_t)(2*h2)  *hs] = rstd*(d0 - mu*Sf[2*h2])   + Cf[2*h2];
        g_bias[base + (size_t)(2*h2+1)*hs] = rstd*(d1 - mu*Sf[2*h2+1]) + Cf[2*h2+1];
    }
}

__device__ __forceinline__ float shfl_max16(float v) {
    v = fmaxf(v, __shfl_xor_sync(0xffffffffu, v, 8));
    v = fmaxf(v, __shfl_xor_sync(0xffffffffu, v, 4));
    v = fmaxf(v, __shfl_xor_sync(0xffffffffu, v, 2));
    v = fmaxf(v, __shfl_xor_sync(0xffffffffu, v, 1));
    return v;
}
__device__ __forceinline__ float shfl_sum16(float v) {
    v += __shfl_xor_sync(0xffffffffu, v, 8);
    v += __shfl_xor_sync(0xffffffffu, v, 4);
    v += __shfl_xor_sync(0xffffffffu, v, 2);
    v += __shfl_xor_sync(0xffffffffu, v, 1);
    return v;
}

// K3: flash attention with pair bias + mask + gating (scores never hit HBM).
// Block = one (b,h,i-tile of 64 rows). Streams 64-wide j tiles; online softmax.
__global__ void __launch_bounds__(256) attn_kernel(const float* __restrict__ mask)
{
    extern __shared__ float sm[];
    float* qs = sm;                       // [48][64]  qs[d*IT + i]
    float* ks = sm + 48*IT;               // [48][64]  ks[d*JT + j]
    float* vs = ks + 48*JT;               // [64][48]  vs[j*48 + d]
    float* ps = vs + JT*48;               // [64][PSS]
    float* scale_s = ps + IT*PSS;         // [64]
    float* l_s = scale_s + IT;            // [64]

    const int tid = threadIdx.x;
    const int h  = blockIdx.y & (HH-1);
    const int b  = blockIdx.y >> 4;
    const int i0 = blockIdx.x * IT;
    const int tx = tid & 15, ty = tid >> 4;   // S layout: 4 rows x 4 cols
    const int tx2 = tid & 7, ty2 = tid >> 3;  // PV layout: 2 rows x 6 cols

    // load q tile transposed (once)
    for (int idx = tid; idx < IT * (HD/4); idx += 256) {
        const int r = idx / (HD/4), dq = idx % (HD/4);
        float4 v = *(const float4*)&g_q[((size_t)(b*NN + i0 + r))*CS + h*HD + dq*4];
        qs[(dq*4+0)*IT + r] = v.x; qs[(dq*4+1)*IT + r] = v.y;
        qs[(dq*4+2)*IT + r] = v.z; qs[(dq*4+3)*IT + r] = v.w;
    }

    float mrow[4] = {-1e30f, -1e30f, -1e30f, -1e30f};
    float lrow[4] = {0.f, 0.f, 0.f, 0.f};
    ull oacc[2][3];
#pragma unroll
    for (int r = 0; r < 2; r++)
#pragma unroll
        for (int c = 0; c < 3; c++) oacc[r][c] = 0ULL;

    const size_t bh = ((size_t)b*HH + h) * (size_t)NN * NN;
    const float scale = 0.14433756729740643f;   // 1/sqrt(48)

    for (int jt = 0; jt < NN / JT; jt++) {
        const int j0 = jt * JT;
        __syncthreads();   // prev PV done with ps/vs

        // load k tile (transposed) + v tile
        for (int idx = tid; idx < JT * (HD/4); idx += 256) {
            const int j = idx / (HD/4), dq = idx % (HD/4);
            const size_t go = ((size_t)(b*NN + j0 + j))*CS + h*HD + dq*4;
            float4 kv = *(const float4*)&g_k[go];
            ks[(dq*4+0)*JT + j] = kv.x; ks[(dq*4+1)*JT + j] = kv.y;
            ks[(dq*4+2)*JT + j] = kv.z; ks[(dq*4+3)*JT + j] = kv.w;
            float4 vv = *(const float4*)&g_v[go];
            *(float4*)&vs[j*48 + dq*4] = vv;
        }
        __syncthreads();

        // ---- S phase: 4 rows x 4 cols per thread ----
        ull acc[4][2];
#pragma unroll
        for (int i = 0; i < 4; i++) { acc[i][0] = 0ULL; acc[i][1] = 0ULL; }

#pragma unroll 4
        for (int d = 0; d < HD; d++) {
            float4 a = *(const float4*)&qs[d*IT + ty*4];
            ulonglong2 kb = *(const ulonglong2*)&ks[d*JT + tx*4];
            float av[4] = {a.x, a.y, a.z, a.w};
#pragma unroll
            for (int i = 0; i < 4; i++) {
                ull ad = dup2(av[i]);
                fma2(acc[i][0], ad, kb.x);
                fma2(acc[i][1], ad, kb.y);
            }
        }

        float4 mk = *(const float4*)&mask[b*NN + j0 + tx*4];
        float madd[4] = {(1.f-mk.x)*(-1e6f), (1.f-mk.y)*(-1e6f),
                         (1.f-mk.z)*(-1e6f), (1.f-mk.w)*(-1e6f)};

#pragma unroll
        for (int i = 0; i < 4; i++) {
            const int row = ty*4 + i;
            float sv[4];
            unpack2(acc[i][0], sv[0], sv[1]);
            unpack2(acc[i][1], sv[2], sv[3]);
            float4 bb = *(const float4*)&g_bias[bh + (size_t)(i0+row)*NN + j0 + tx*4];
            sv[0] = fmaf(sv[0], scale, bb.x + madd[0]);
            sv[1] = fmaf(sv[1], scale, bb.y + madd[1]);
            sv[2] = fmaf(sv[2], scale, bb.z + madd[2]);
            sv[3] = fmaf(sv[3], scale, bb.w + madd[3]);

            float rm = fmaxf(fmaxf(sv[0], sv[1]), fmaxf(sv[2], sv[3]));
            rm = shfl_max16(rm);
            float mn = fmaxf(mrow[i], rm);
            float p0 = __expf(sv[0] - mn), p1 = __expf(sv[1] - mn);
            float p2 = __expf(sv[2] - mn), p3 = __expf(sv[3] - mn);
            float rs = shfl_sum16(p0 + p1 + p2 + p3);
            float sc = __expf(mrow[i] - mn);
            lrow[i] = lrow[i] * sc + rs;
            mrow[i] = mn;
            *(float4*)&ps[row*PSS + tx*4] = make_float4(p0, p1, p2, p3);
            if (tx == 0) scale_s[row] = sc;
        }
        __syncthreads();

        // ---- PV phase: 2 rows x 6 cols per thread ----
        {
            const int r0 = ty2*2, r1 = ty2*2 + 1;
            ull d0 = dup2(scale_s[r0]);
            ull d1 = dup2(scale_s[r1]);
#pragma unroll
            for (int c = 0; c < 3; c++) { mul2(oacc[0][c], d0); mul2(oacc[1][c], d1); }

            const float* vbase = vs + tx2*6;
#pragma unroll 4
            for (int k = 0; k < JT; k += 2) {
                ull pk0 = *(const ull*)&ps[r0*PSS + k];
                ull pk1 = *(const ull*)&ps[r1*PSS + k];
                float p00, p01, p10, p11;
                unpack2(pk0, p00, p01);
                unpack2(pk1, p10, p11);
                const float* v0 = vbase + k*48;
                const float* v1 = v0 + 48;
                ull va0 = *(const ull*)(v0);
                ull va1 = *(const ull*)(v0 + 2);
                ull va2 = *(const ull*)(v0 + 4);
                ull vb0 = *(const ull*)(v1);
                ull vb1 = *(const ull*)(v1 + 2);
                ull vb2 = *(const ull*)(v1 + 4);
                ull a00 = dup2(p00), a10 = dup2(p10);
                fma2(oacc[0][0], a00, va0); fma2(oacc[0][1], a00, va1); fma2(oacc[0][2], a00, va2);
                fma2(oacc[1][0], a10, va0); fma2(oacc[1][1], a10, va1); fma2(oacc[1][2], a10, va2);
                ull a01 = dup2(p01), a11 = dup2(p11);
                fma2(oacc[0][0], a01, vb0); fma2(oacc[0][1], a01, vb1); fma2(oacc[0][2], a01, vb2);
                fma2(oacc[1][0], a11, vb0); fma2(oacc[1][1], a11, vb1); fma2(oacc[1][2], a11, vb2);
            }
        }
    }

    // publish l for PV-layout threads
    if (tx == 0) {
#pragma unroll
        for (int i = 0; i < 4; i++) l_s[ty*4 + i] = lrow[i];
    }
    __syncthreads();

    // epilogue: divide by l, gate, store
#pragma unroll
    for (int r = 0; r < 2; r++) {
        const int row = ty2*2 + r;
        const float inv = 1.f / l_s[row];
        const size_t off = ((size_t)(b*NN + i0 + row))*CS + h*HD + tx2*6;
#pragma unroll
        for (int c = 0; c < 3; c++) {
            float o0, o1;
            unpack2(oacc[r][c], o0, o1);
            float gg0 = g_g[off + 2*c], gg1 = g_g[off + 2*c + 1];
            *(ull*)&g_og[off + 2*c] = pack2(o0 * inv * gg0, o1 * inv * gg1);
        }
    }
}

extern "C" void kernel_launch(void* const* d_in, const int* in_sizes, int n_in,
                              void* d_out, int out_size)
{
    const float* s    = (const float*)d_in[0];
    const float* z    = (const float*)d_in[1];
    const float* mask = (const float*)d_in[2];
    const float* kin  = (const float*)d_in[3];
    const float* Wq   = (const float*)d_in[4];
    const float* bq   = (const float*)d_in[5];
    const float* Wk   = (const float*)d_in[6];
    const float* Wv   = (const float*)d_in[7];
    const float* Wg   = (const float*)d_in[8];
    const float* lng  = (const float*)d_in[9];
    const float* lnb  = (const float*)d_in[10];
    const float* Wz   = (const float*)d_in[11];
    const float* Wo   = (const float*)d_in[12];
    float* out = (float*)d_out;

    const int attn_smem = (48*IT + 48*JT + JT*48 + IT*PSS + IT + IT) * 4;
    cudaFuncSetAttribute(attn_kernel,
                         cudaFuncAttributeMaxDynamicSharedMemorySize, attn_smem);

    qkvg_kernel<<<dim3(CS/128, BB*NN/128, 4), 256>>>(s, kin, Wq, bq, Wk, Wv, Wg);
    biasproj_kernel<<<BB*NN*NN/256, 256>>>(z, lng, lnb, Wz);
    attn_kernel<<<dim3(NN/IT, BB*HH), 256, attn_smem>>>(mask);
    outproj_partial_kernel<<<dim3(CS/128, BB*NN/128, 4), 256>>>(Wo);
    reduce4_kernel<<<(BB*NN*CS/4)/256, 256>>>(out);
}

// round 12
// speedup vs baseline: 1.3770x; 1.0640x over previous
#include <cuda_runtime.h>
#include <cstdint>

typedef unsigned long long ull;

#define BB 2
#define NN 768
#define CS 768
#define HH 16
#define HD 48
#define CZ 128

#define IT 64      // attention i-tile rows
#define JT 64      // attention j-tile cols
#define PSS 68     // P tile row stride (pad for banks, keeps 8B align)
#define WSP 140    // padded Ws row stride: col' = c + (c>>5)*4, conflict-free

// ----- scratch (static device globals: no allocation allowed) -----
__device__ float g_q [BB*NN*CS];
__device__ float g_k [BB*NN*CS];
__device__ float g_v [BB*NN*CS];
__device__ float g_g [BB*NN*CS];
__device__ float g_og[BB*NN*CS];
__device__ float g_bias[(size_t)BB*HH*NN*NN];

// ----- packed f32x2 helpers -----
__device__ __forceinline__ ull pack2(float x, float y) {
    ull r; asm("mov.b64 %0, {%1, %2};" : "=l"(r) : "f"(x), "f"(y)); return r;
}
__device__ __forceinline__ ull dup2(float x) { return pack2(x, x); }
__device__ __forceinline__ void fma2(ull& d, ull a, ull b) {
    asm("fma.rn.f32x2 %0, %1, %2, %0;" : "+l"(d) : "l"(a), "l"(b));
}
__device__ __forceinline__ void mul2(ull& d, ull a) {
    asm("mul.rn.f32x2 %0, %0, %1;" : "+l"(d) : "l"(a));
}
__device__ __forceinline__ void unpack2(ull v, float& x, float& y) {
    asm("mov.b64 {%0, %1}, %2;" : "=f"(x), "=f"(y) : "l"(v));
}

// ----- 128x128 tiled GEMM, BK=16, 256 threads, 8x8/thread, double-buffered,
// Ws columns padded (c' = c + (c>>5)*4) for conflict-free stride-8 LDS.128. --
__device__ __forceinline__ void gemm_block(
    const float* __restrict__ A, const float* __restrict__ W,
    const float* __restrict__ bvec, float* __restrict__ C, int act,
    int m0, int n0, int kbeg, int ktiles)
{
    __shared__ __align__(16) float As[2][16][128];
    __shared__ __align__(16) float Ws[2][16][WSP];
    const int tid = threadIdx.x;
    const int lr = tid >> 1;
    const int lq = (tid & 1) * 8;
    const int tx = tid & 15, ty = tid >> 4;
    const int lrp = lr + ((lr >> 5) << 2);          // padded write col
    const int txp = tx * 8 + ((tx >> 2) << 2);      // padded read col

    const float* ap = A + (size_t)(m0 + lr) * CS + kbeg + lq;
    const float* wp = W + (size_t)(n0 + lr) * CS + kbeg + lq;

    ull acc[8][4];
#pragma unroll
    for (int i = 0; i < 8; i++)
#pragma unroll
        for (int j = 0; j < 4; j++) acc[i][j] = 0ULL;

    float4 a0 = *(const float4*)ap;
    float4 a1 = *(const float4*)(ap + 4);
    float4 w0 = *(const float4*)wp;
    float4 w1 = *(const float4*)(wp + 4);

    for (int kt = 0; kt < ktiles; kt++) {
        const int buf = kt & 1;
        As[buf][lq+0][lr]=a0.x; As[buf][lq+1][lr]=a0.y;
        As[buf][lq+2][lr]=a0.z; As[buf][lq+3][lr]=a0.w;
        As[buf][lq+4][lr]=a1.x; As[buf][lq+5][lr]=a1.y;
        As[buf][lq+6][lr]=a1.z; As[buf][lq+7][lr]=a1.w;
        Ws[buf][lq+0][lrp]=w0.x; Ws[buf][lq+1][lrp]=w0.y;
        Ws[buf][lq+2][lrp]=w0.z; Ws[buf][lq+3][lrp]=w0.w;
        Ws[buf][lq+4][lrp]=w1.x; Ws[buf][lq+5][lrp]=w1.y;
        Ws[buf][lq+6][lrp]=w1.z; Ws[buf][lq+7][lrp]=w1.w;
        __syncthreads();

        if (kt + 1 < ktiles) {                  // prefetch next k-tile
            const int ko = (kt + 1) * 16;
            a0 = *(const float4*)(ap + ko);
            a1 = *(const float4*)(ap + ko + 4);
            w0 = *(const float4*)(wp + ko);
            w1 = *(const float4*)(wp + ko + 4);
        }

#pragma unroll
        for (int k = 0; k < 16; k++) {
            float4 fa0 = *(const float4*)&As[buf][k][ty*8];
            float4 fa1 = *(const float4*)&As[buf][k][ty*8+4];
            ulonglong2 b01 = *(const ulonglong2*)&Ws[buf][k][txp];
            ulonglong2 b23 = *(const ulonglong2*)&Ws[buf][k][txp+4];
            float av[8] = {fa0.x,fa0.y,fa0.z,fa0.w,fa1.x,fa1.y,fa1.z,fa1.w};
#pragma unroll
            for (int i = 0; i < 8; i++) {
                ull ad = dup2(av[i]);
                fma2(acc[i][0], ad, b01.x);
                fma2(acc[i][1], ad, b01.y);
                fma2(acc[i][2], ad, b23.x);
                fma2(acc[i][3], ad, b23.y);
            }
        }
        // no trailing barrier: next STS targets the other buffer.
    }

    float bv[8];
    if (bvec) {
        float4 b0 = *(const float4*)&bvec[n0 + tx*8];
        float4 b1 = *(const float4*)&bvec[n0 + tx*8 + 4];
        bv[0]=b0.x; bv[1]=b0.y; bv[2]=b0.z; bv[3]=b0.w;
        bv[4]=b1.x; bv[5]=b1.y; bv[6]=b1.z; bv[7]=b1.w;
    } else {
#pragma unroll
        for (int c = 0; c < 8; c++) bv[c] = 0.f;
    }

#pragma unroll
    for (int i = 0; i < 8; i++) {
        float r[8];
#pragma unroll
        for (int j = 0; j < 4; j++) unpack2(acc[i][j], r[2*j], r[2*j+1]);
#pragma unroll
        for (int c = 0; c < 8; c++) {
            r[c] += bv[c];
            if (act) r[c] = 1.f / (1.f + __expf(-r[c]));
        }
        float* cp = C + (size_t)(m0 + ty*8 + i) * CS + n0 + tx*8;
        *(float4*)cp     = make_float4(r[0], r[1], r[2], r[3]);
        *(float4*)(cp+4) = make_float4(r[4], r[5], r[6], r[7]);
    }
}

// K1: q/k/v/g projections
__global__ void __launch_bounds__(256) qkvg_kernel(
    const float* __restrict__ s,  const float* __restrict__ kin,
    const float* __restrict__ Wq, const float* __restrict__ bq,
    const float* __restrict__ Wk, const float* __restrict__ Wv,
    const float* __restrict__ Wg)
{
    const float* A; const float* W; const float* bv = nullptr;
    float* C; int act = 0;
    switch (blockIdx.z) {
        case 0:  A = s;   W = Wq; bv = bq; C = g_q; break;
        case 1:  A = kin; W = Wk;          C = g_k; break;
        case 2:  A = kin; W = Wv;          C = g_v; break;
        default: A = s;   W = Wg;          C = g_g; act = 1; break;
    }
    gemm_block(A, W, bv, C, act, blockIdx.y * 128, blockIdx.x * 128, 0, CS/16);
}

// K4: out partials = og @ Wo^T over K-quarter, into dead q/k/v/g scratch.
__global__ void __launch_bounds__(256) outproj_partial_kernel(
    const float* __restrict__ Wo)
{
    float* part;
    switch (blockIdx.z) {
        case 0:  part = g_q; break;
        case 1:  part = g_k; break;
        case 2:  part = g_v; break;
        default: part = g_g; break;
    }
    gemm_block(g_og, Wo, nullptr, part, 0,
               blockIdx.y * 128, blockIdx.x * 128,
               blockIdx.z * (CS/4), (CS/4)/16);
}

// K5: out = p0+p1+p2+p3
__global__ void __launch_bounds__(256) reduce4_kernel(float* __restrict__ out)
{
    const int i = blockIdx.x * 256 + threadIdx.x;
    float4 a = ((const float4*)g_q)[i];
    float4 b = ((const float4*)g_k)[i];
    float4 c = ((const float4*)g_v)[i];
    float4 d = ((const float4*)g_g)[i];
    ((float4*)out)[i] = make_float4(a.x+b.x+c.x+d.x, a.y+b.y+c.y+d.y,
                                    a.z+b.z+c.z+d.z, a.w+b.w+c.w+d.w);
}

// K2: bias[b,h,i,j] = LayerNorm(z[b,i,j,:]) . Wz[h,:]  (coalesced via smem)
__global__ void __launch_bounds__(256) biasproj_kernel(
    const float* __restrict__ z,   const float* __restrict__ lng,
    const float* __restrict__ lnb, const float* __restrict__ Wz)
{
    __shared__ __align__(16) ull A2[128][8];   // {g_c*Wz[2h], g_c*Wz[2h+1]}
    __shared__ float Sf[16], Cf[16];
    __shared__ __align__(16) float zt[256][36];
    const int tid = threadIdx.x;
    if (tid < 128) {
        float gc = lng[tid];
#pragma unroll
        for (int h2 = 0; h2 < 8; h2++)
            A2[tid][h2] = pack2(gc * Wz[(2*h2)*CZ + tid], gc * Wz[(2*h2+1)*CZ + tid]);
    } else if (tid < 144) {
        int hh = tid - 128;
        float S = 0.f, Cc = 0.f;
        for (int c = 0; c < CZ; c++) {
            float w = Wz[hh*CZ + c];
            S  = fmaf(lng[c], w, S);
            Cc = fmaf(lnb[c], w, Cc);
        }
        Sf[hh] = S; Cf[hh] = Cc;
    }
    __syncthreads();

    const int row0 = blockIdx.x * 256;
    const int row  = row0 + tid;
    const int j = row % NN;
    const int t = row / NN;
    const int i = t % NN;
    const int b = t / NN;

    ull acc[8];
#pragma unroll
    for (int h2 = 0; h2 < 8; h2++) acc[h2] = 0ULL;
    float sum = 0.f, sumsq = 0.f;

    for (int ct = 0; ct < CZ/32; ct++) {
#pragma unroll
        for (int u = 0; u < 8; u++) {
            const int idx = u * 256 + tid;
            const int r = idx >> 3, q = idx & 7;
            *(float4*)&zt[r][q*4] =
                *(const float4*)&z[(size_t)(row0 + r)*CZ + ct*32 + q*4];
        }
        __syncthreads();

#pragma unroll
        for (int cq = 0; cq < 8; cq++) {
            float4 zv = *(const float4*)&zt[tid][cq*4];
            float zz[4] = {zv.x, zv.y, zv.z, zv.w};
#pragma unroll
            for (int u = 0; u < 4; u++) {
                const int c = ct*32 + cq*4 + u;
                float zc = zz[u];
                sum += zc;
                sumsq = fmaf(zc, zc, sumsq);
                ull zd = dup2(zc);
                const ulonglong2* ap = (const ulonglong2*)&A2[c][0];
                ulonglong2 a01 = ap[0], a23 = ap[1], a45 = ap[2], a67 = ap[3];
                fma2(acc[0], zd, a01.x); fma2(acc[1], zd, a01.y);
                fma2(acc[2], zd, a23.x); fma2(acc[3], zd, a23.y);
                fma2(acc[4], zd, a45.x); fma2(acc[5], zd, a45.y);
                fma2(acc[6], zd, a67.x); fma2(acc[7], zd, a67.y);
            }
        }
        __syncthreads();
    }

    const float inv = 1.f / CZ;
    float mu   = sum * inv;
    float var  = sumsq * inv - mu*mu;
    float rstd = rsqrtf(var + 1e-5f);

    const size_t base = ((size_t)b*HH*NN + i) * NN + j;
    const size_t hs   = (size_t)NN * NN;
#pragma unroll
    for (int h2 = 0; h2 < 8; h2++) {
        float d0, d1; unpack2(acc[h2], d0, d1);
        g_bias[base + (size_t)(2*h2)  *hs] = rstd*(d0 - mu*Sf[2*h2])   + Cf[2*h2];
        g_bias[base + (size_t)(2*h2+1)*hs] = rstd*(d1 - mu*Sf[2*h2+1]) + Cf[2*h2+1];
    }
}

__device__ __forceinline__ float shfl_max16(float v) {
    v = fmaxf(v, __shfl_xor_sync(0xffffffffu, v, 8));
    v = fmaxf(v, __shfl_xor_sync(0xffffffffu, v, 4));
    v = fmaxf(v, __shfl_xor_sync(0xffffffffu, v, 2));
    v = fmaxf(v, __shfl_xor_sync(0xffffffffu, v, 1));
    return v;
}
__device__ __forceinline__ float shfl_sum16(float v) {
    v += __shfl_xor_sync(0xffffffffu, v, 8);
    v += __shfl_xor_sync(0xffffffffu, v, 4);
    v += __shfl_xor_sync(0xffffffffu, v, 2);
    v += __shfl_xor_sync(0xffffffffu, v, 1);
    return v;
}

// K3: flash attention with pair bias + mask + gating (scores never hit HBM).
__global__ void __launch_bounds__(256) attn_kernel(const float* __restrict__ mask)
{
    extern __shared__ float sm[];
    float* qs = sm;                       // [48][64]  qs[d*IT + i]
    float* ks = sm + 48*IT;               // [48][64]  ks[d*JT + j]
    float* vs = ks + 48*JT;               // [64][48]  vs[j*48 + d]
    float* ps = vs + JT*48;               // [64][PSS]
    float* scale_s = ps + IT*PSS;         // [64]
    float* l_s = scale_s + IT;            // [64]

    const int tid = threadIdx.x;
    const int h  = blockIdx.y & (HH-1);
    const int b  = blockIdx.y >> 4;
    const int i0 = blockIdx.x * IT;
    const int tx = tid & 15, ty = tid >> 4;   // S layout: 4 rows x 4 cols
    const int tx2 = tid & 7, ty2 = tid >> 3;  // PV layout: 2 rows x 6 cols

    for (int idx = tid; idx < IT * (HD/4); idx += 256) {
        const int r = idx / (HD/4), dq = idx % (HD/4);
        float4 v = *(const float4*)&g_q[((size_t)(b*NN + i0 + r))*CS + h*HD + dq*4];
        qs[(dq*4+0)*IT + r] = v.x; qs[(dq*4+1)*IT + r] = v.y;
        qs[(dq*4+2)*IT + r] = v.z; qs[(dq*4+3)*IT + r] = v.w;
    }

    float mrow[4] = {-1e30f, -1e30f, -1e30f, -1e30f};
    float lrow[4] = {0.f, 0.f, 0.f, 0.f};
    ull oacc[2][3];
#pragma unroll
    for (int r = 0; r < 2; r++)
#pragma unroll
        for (int c = 0; c < 3; c++) oacc[r][c] = 0ULL;

    const size_t bh = ((size_t)b*HH + h) * (size_t)NN * NN;
    const float scale = 0.14433756729740643f;   // 1/sqrt(48)

    for (int jt = 0; jt < NN / JT; jt++) {
        const int j0 = jt * JT;
        __syncthreads();

        for (int idx = tid; idx < JT * (HD/4); idx += 256) {
            const int j = idx / (HD/4), dq = idx % (HD/4);
            const size_t go = ((size_t)(b*NN + j0 + j))*CS + h*HD + dq*4;
            float4 kv = *(const float4*)&g_k[go];
            ks[(dq*4+0)*JT + j] = kv.x; ks[(dq*4+1)*JT + j] = kv.y;
            ks[(dq*4+2)*JT + j] = kv.z; ks[(dq*4+3)*JT + j] = kv.w;
            float4 vv = *(const float4*)&g_v[go];
            *(float4*)&vs[j*48 + dq*4] = vv;
        }
        __syncthreads();

        ull acc[4][2];
#pragma unroll
        for (int i = 0; i < 4; i++) { acc[i][0] = 0ULL; acc[i][1] = 0ULL; }

#pragma unroll 4
        for (int d = 0; d < HD; d++) {
            float4 a = *(const float4*)&qs[d*IT + ty*4];
            ulonglong2 kb = *(const ulonglong2*)&ks[d*JT + tx*4];
            float av[4] = {a.x, a.y, a.z, a.w};
#pragma unroll
            for (int i = 0; i < 4; i++) {
                ull ad = dup2(av[i]);
                fma2(acc[i][0], ad, kb.x);
                fma2(acc[i][1], ad, kb.y);
            }
        }

        float4 mk = *(const float4*)&mask[b*NN + j0 + tx*4];
        float madd[4] = {(1.f-mk.x)*(-1e6f), (1.f-mk.y)*(-1e6f),
                         (1.f-mk.z)*(-1e6f), (1.f-mk.w)*(-1e6f)};

#pragma unroll
        for (int i = 0; i < 4; i++) {
            const int row = ty*4 + i;
            float sv[4];
            unpack2(acc[i][0], sv[0], sv[1]);
            unpack2(acc[i][1], sv[2], sv[3]);
            float4 bb = *(const float4*)&g_bias[bh + (size_t)(i0+row)*NN + j0 + tx*4];
            sv[0] = fmaf(sv[0], scale, bb.x + madd[0]);
            sv[1] = fmaf(sv[1], scale, bb.y + madd[1]);
            sv[2] = fmaf(sv[2], scale, bb.z + madd[2]);
            sv[3] = fmaf(sv[3], scale, bb.w + madd[3]);

            float rm = fmaxf(fmaxf(sv[0], sv[1]), fmaxf(sv[2], sv[3]));
            rm = shfl_max16(rm);
            float mn = fmaxf(mrow[i], rm);
            float p0 = __expf(sv[0] - mn), p1 = __expf(sv[1] - mn);
            float p2 = __expf(sv[2] - mn), p3 = __expf(sv[3] - mn);
            float rs = shfl_sum16(p0 + p1 + p2 + p3);
            float sc = __expf(mrow[i] - mn);
            lrow[i] = lrow[i] * sc + rs;
            mrow[i] = mn;
            *(float4*)&ps[row*PSS + tx*4] = make_float4(p0, p1, p2, p3);
            if (tx == 0) scale_s[row] = sc;
        }
        __syncthreads();

        {
            const int r0 = ty2*2, r1 = ty2*2 + 1;
            ull d0 = dup2(scale_s[r0]);
            ull d1 = dup2(scale_s[r1]);
#pragma unroll
            for (int c = 0; c < 3; c++) { mul2(oacc[0][c], d0); mul2(oacc[1][c], d1); }

            const float* vbase = vs + tx2*6;
#pragma unroll 4
            for (int k = 0; k < JT; k += 2) {
                ull pk0 = *(const ull*)&ps[r0*PSS + k];
                ull pk1 = *(const ull*)&ps[r1*PSS + k];
                float p00, p01, p10, p11;
                unpack2(pk0, p00, p01);
                unpack2(pk1, p10, p11);
                const float* v0 = vbase + k*48;
                const float* v1 = v0 + 48;
                ull va0 = *(const ull*)(v0);
                ull va1 = *(const ull*)(v0 + 2);
                ull va2 = *(const ull*)(v0 + 4);
                ull vb0 = *(const ull*)(v1);
                ull vb1 = *(const ull*)(v1 + 2);
                ull vb2 = *(const ull*)(v1 + 4);
                ull a00 = dup2(p00), a10 = dup2(p10);
                fma2(oacc[0][0], a00, va0); fma2(oacc[0][1], a00, va1); fma2(oacc[0][2], a00, va2);
                fma2(oacc[1][0], a10, va0); fma2(oacc[1][1], a10, va1); fma2(oacc[1][2], a10, va2);
                ull a01 = dup2(p01), a11 = dup2(p11);
                fma2(oacc[0][0], a01, vb0); fma2(oacc[0][1], a01, vb1); fma2(oacc[0][2], a01, vb2);
                fma2(oacc[1][0], a11, vb0); fma2(oacc[1][1], a11, vb1); fma2(oacc[1][2], a11, vb2);
            }
        }
    }

    if (tx == 0) {
#pragma unroll
        for (int i = 0; i < 4; i++) l_s[ty*4 + i] = lrow[i];
    }
    __syncthreads();

#pragma unroll
    for (int r = 0; r < 2; r++) {
        const int row = ty2*2 + r;
        const float inv = 1.f / l_s[row];
        const size_t off = ((size_t)(b*NN + i0 + row))*CS + h*HD + tx2*6;
#pragma unroll
        for (int c = 0; c < 3; c++) {
            float o0, o1;
            unpack2(oacc[r][c], o0, o1);
            float gg0 = g_g[off + 2*c], gg1 = g_g[off + 2*c + 1];
            *(ull*)&g_og[off + 2*c] = pack2(o0 * inv * gg0, o1 * inv * gg1);
        }
    }
}

extern "C" void kernel_launch(void* const* d_in, const int* in_sizes, int n_in,
                              void* d_out, int out_size)
{
    const float* s    = (const float*)d_in[0];
    const float* z    = (const float*)d_in[1];
    const float* mask = (const float*)d_in[2];
    const float* kin  = (const float*)d_in[3];
    const float* Wq   = (const float*)d_in[4];
    const float* bq   = (const float*)d_in[5];
    const float* Wk   = (const float*)d_in[6];
    const float* Wv   = (const float*)d_in[7];
    const float* Wg   = (const float*)d_in[8];
    const float* lng  = (const float*)d_in[9];
    const float* lnb  = (const float*)d_in[10];
    const float* Wz   = (const float*)d_in[11];
    const float* Wo   = (const float*)d_in[12];
    float* out = (float*)d_out;

    const int attn_smem = (48*IT + 48*JT + JT*48 + IT*PSS + IT + IT) * 4;
    cudaFuncSetAttribute(attn_kernel,
                         cudaFuncAttributeMaxDynamicSharedMemorySize, attn_smem);

    // fork: run biasproj (DRAM-bound) concurrently with qkvg (fma-bound).
    // NOTE: stream/events are intentionally NOT destroyed here — destroying a
    // stream that participates in an active capture invalidates the capture.
    // kernel_launch runs only a handful of times (correctness + capture), so
    // the handle leak is bounded and each call does identical work.
    cudaStream_t s2;
    cudaStreamCreateWithFlags(&s2, cudaStreamNonBlocking);
    cudaEvent_t eFork, eJoin;
    cudaEventCreateWithFlags(&eFork, cudaEventDisableTiming);
    cudaEventCreateWithFlags(&eJoin, cudaEventDisableTiming);

    cudaEventRecord(eFork, 0);
    cudaStreamWaitEvent(s2, eFork, 0);

    qkvg_kernel<<<dim3(CS/128, BB*NN/128, 4), 256>>>(s, kin, Wq, bq, Wk, Wv, Wg);
    biasproj_kernel<<<BB*NN*NN/256, 256, 0, s2>>>(z, lng, lnb, Wz);

    cudaEventRecord(eJoin, s2);
    cudaStreamWaitEvent(0, eJoin, 0);

    attn_kernel<<<dim3(NN/IT, BB*HH), 256, attn_smem>>>(mask);
    outproj_partial_kernel<<<dim3(CS/128, BB*NN/128, 4), 256>>>(Wo);
    reduce4_kernel<<<(BB*NN*CS/4)/256, 256>>>(out);
}

// round 14
// speedup vs baseline: 1.3839x; 1.0050x over previous
#include <cuda_runtime.h>
#include <cstdint>

typedef unsigned long long ull;

#define BB 2
#define NN 768
#define CS 768
#define HH 16
#define HD 48
#define CZ 128

#define IT 64      // attention i-tile rows
#define JT 64      // attention j-tile cols
#define NJT (NN/JT)
#define PSS 68     // P tile row stride (pad for banks, keeps 8B align)
#define WSP 140    // padded Ws row stride: col' = c + (c>>5)*4, conflict-free

// ----- scratch (static device globals: no allocation allowed) -----
__device__ float g_q [BB*NN*CS];
__device__ float g_k [BB*NN*CS];
__device__ float g_v [BB*NN*CS];
__device__ float g_g [BB*NN*CS];
__device__ float g_og[BB*NN*CS];
__device__ float g_bias[(size_t)BB*HH*NN*NN];

// ----- packed f32x2 helpers -----
__device__ __forceinline__ ull pack2(float x, float y) {
    ull r; asm("mov.b64 %0, {%1, %2};" : "=l"(r) : "f"(x), "f"(y)); return r;
}
__device__ __forceinline__ ull dup2(float x) { return pack2(x, x); }
__device__ __forceinline__ void fma2(ull& d, ull a, ull b) {
    asm("fma.rn.f32x2 %0, %1, %2, %0;" : "+l"(d) : "l"(a), "l"(b));
}
__device__ __forceinline__ void mul2(ull& d, ull a) {
    asm("mul.rn.f32x2 %0, %0, %1;" : "+l"(d) : "l"(a));
}
__device__ __forceinline__ void unpack2(ull v, float& x, float& y) {
    asm("mov.b64 {%0, %1}, %2;" : "=f"(x), "=f"(y) : "l"(v));
}

// ----- 128x128 tiled GEMM, BK=16, 256 threads, 8x8/thread, double-buffered,
// Ws columns padded (c' = c + (c>>5)*4) for conflict-free stride-8 LDS.128. --
__device__ __forceinline__ void gemm_block(
    const float* __restrict__ A, const float* __restrict__ W,
    const float* __restrict__ bvec, float* __restrict__ C, int act,
    int m0, int n0, int kbeg, int ktiles)
{
    __shared__ __align__(16) float As[2][16][128];
    __shared__ __align__(16) float Ws[2][16][WSP];
    const int tid = threadIdx.x;
    const int lr = tid >> 1;
    const int lq = (tid & 1) * 8;
    const int tx = tid & 15, ty = tid >> 4;
    const int lrp = lr + ((lr >> 5) << 2);          // padded write col
    const int txp = tx * 8 + ((tx >> 2) << 2);      // padded read col

    const float* ap = A + (size_t)(m0 + lr) * CS + kbeg + lq;
    const float* wp = W + (size_t)(n0 + lr) * CS + kbeg + lq;

    ull acc[8][4];
#pragma unroll
    for (int i = 0; i < 8; i++)
#pragma unroll
        for (int j = 0; j < 4; j++) acc[i][j] = 0ULL;

    float4 a0 = *(const float4*)ap;
    float4 a1 = *(const float4*)(ap + 4);
    float4 w0 = *(const float4*)wp;
    float4 w1 = *(const float4*)(wp + 4);

    for (int kt = 0; kt < ktiles; kt++) {
        const int buf = kt & 1;
        As[buf][lq+0][lr]=a0.x; As[buf][lq+1][lr]=a0.y;
        As[buf][lq+2][lr]=a0.z; As[buf][lq+3][lr]=a0.w;
        As[buf][lq+4][lr]=a1.x; As[buf][lq+5][lr]=a1.y;
        As[buf][lq+6][lr]=a1.z; As[buf][lq+7][lr]=a1.w;
        Ws[buf][lq+0][lrp]=w0.x; Ws[buf][lq+1][lrp]=w0.y;
        Ws[buf][lq+2][lrp]=w0.z; Ws[buf][lq+3][lrp]=w0.w;
        Ws[buf][lq+4][lrp]=w1.x; Ws[buf][lq+5][lrp]=w1.y;
        Ws[buf][lq+6][lrp]=w1.z; Ws[buf][lq+7][lrp]=w1.w;
        __syncthreads();

        if (kt + 1 < ktiles) {                  // prefetch next k-tile
            const int ko = (kt + 1) * 16;
            a0 = *(const float4*)(ap + ko);
            a1 = *(const float4*)(ap + ko + 4);
            w0 = *(const float4*)(wp + ko);
            w1 = *(const float4*)(wp + ko + 4);
        }

#pragma unroll
        for (int k = 0; k < 16; k++) {
            float4 fa0 = *(const float4*)&As[buf][k][ty*8];
            float4 fa1 = *(const float4*)&As[buf][k][ty*8+4];
            ulonglong2 b01 = *(const ulonglong2*)&Ws[buf][k][txp];
            ulonglong2 b23 = *(const ulonglong2*)&Ws[buf][k][txp+4];
            float av[8] = {fa0.x,fa0.y,fa0.z,fa0.w,fa1.x,fa1.y,fa1.z,fa1.w};
#pragma unroll
            for (int i = 0; i < 8; i++) {
                ull ad = dup2(av[i]);
                fma2(acc[i][0], ad, b01.x);
                fma2(acc[i][1], ad, b01.y);
                fma2(acc[i][2], ad, b23.x);
                fma2(acc[i][3], ad, b23.y);
            }
        }
        // no trailing barrier: next STS targets the other buffer.
    }

    float bv[8];
    if (bvec) {
        float4 b0 = *(const float4*)&bvec[n0 + tx*8];
        float4 b1 = *(const float4*)&bvec[n0 + tx*8 + 4];
        bv[0]=b0.x; bv[1]=b0.y; bv[2]=b0.z; bv[3]=b0.w;
        bv[4]=b1.x; bv[5]=b1.y; bv[6]=b1.z; bv[7]=b1.w;
    } else {
#pragma unroll
        for (int c = 0; c < 8; c++) bv[c] = 0.f;
    }

#pragma unroll
    for (int i = 0; i < 8; i++) {
        float r[8];
#pragma unroll
        for (int j = 0; j < 4; j++) unpack2(acc[i][j], r[2*j], r[2*j+1]);
#pragma unroll
        for (int c = 0; c < 8; c++) {
            r[c] += bv[c];
            if (act) r[c] = 1.f / (1.f + __expf(-r[c]));
        }
        float* cp = C + (size_t)(m0 + ty*8 + i) * CS + n0 + tx*8;
        *(float4*)cp     = make_float4(r[0], r[1], r[2], r[3]);
        *(float4*)(cp+4) = make_float4(r[4], r[5], r[6], r[7]);
    }
}

// K1: q/k/v/g projections
__global__ void __launch_bounds__(256) qkvg_kernel(
    const float* __restrict__ s,  const float* __restrict__ kin,
    const float* __restrict__ Wq, const float* __restrict__ bq,
    const float* __restrict__ Wk, const float* __restrict__ Wv,
    const float* __restrict__ Wg)
{
    const float* A; const float* W; const float* bv = nullptr;
    float* C; int act = 0;
    switch (blockIdx.z) {
        case 0:  A = s;   W = Wq; bv = bq; C = g_q; break;
        case 1:  A = kin; W = Wk;          C = g_k; break;
        case 2:  A = kin; W = Wv;          C = g_v; break;
        default: A = s;   W = Wg;          C = g_g; act = 1; break;
    }
    gemm_block(A, W, bv, C, act, blockIdx.y * 128, blockIdx.x * 128, 0, CS/16);
}

// K4: out partials = og @ Wo^T over K-quarter, into dead q/k/v/g scratch.
__global__ void __launch_bounds__(256) outproj_partial_kernel(
    const float* __restrict__ Wo)
{
    float* part;
    switch (blockIdx.z) {
        case 0:  part = g_q; break;
        case 1:  part = g_k; break;
        case 2:  part = g_v; break;
        default: part = g_g; break;
    }
    gemm_block(g_og, Wo, nullptr, part, 0,
               blockIdx.y * 128, blockIdx.x * 128,
               blockIdx.z * (CS/4), (CS/4)/16);
}

// K5: out = p0+p1+p2+p3
__global__ void __launch_bounds__(256) reduce4_kernel(float* __restrict__ out)
{
    const int i = blockIdx.x * 256 + threadIdx.x;
    float4 a = ((const float4*)g_q)[i];
    float4 b = ((const float4*)g_k)[i];
    float4 c = ((const float4*)g_v)[i];
    float4 d = ((const float4*)g_g)[i];
    ((float4*)out)[i] = make_float4(a.x+b.x+c.x+d.x, a.y+b.y+c.y+d.y,
                                    a.z+b.z+c.z+d.z, a.w+b.w+c.w+d.w);
}

// K2: bias[b,h,i,j] = LayerNorm(z[b,i,j,:]) . Wz[h,:]  (coalesced via smem)
__global__ void __launch_bounds__(256) biasproj_kernel(
    const float* __restrict__ z,   const float* __restrict__ lng,
    const float* __restrict__ lnb, const float* __restrict__ Wz)
{
    __shared__ __align__(16) ull A2[128][8];
    __shared__ float Sf[16], Cf[16];
    __shared__ __align__(16) float zt[256][36];
    const int tid = threadIdx.x;
    if (tid < 128) {
        float gc = lng[tid];
#pragma unroll
        for (int h2 = 0; h2 < 8; h2++)
            A2[tid][h2] = pack2(gc * Wz[(2*h2)*CZ + tid], gc * Wz[(2*h2+1)*CZ + tid]);
    } else if (tid < 144) {
        int hh = tid - 128;
        float S = 0.f, Cc = 0.f;
        for (int c = 0; c < CZ; c++) {
            float w = Wz[hh*CZ + c];
            S  = fmaf(lng[c], w, S);
            Cc = fmaf(lnb[c], w, Cc);
        }
        Sf[hh] = S; Cf[hh] = Cc;
    }
    __syncthreads();

    const int row0 = blockIdx.x * 256;
    const int row  = row0 + tid;
    const int j = row % NN;
    const int t = row / NN;
    const int i = t % NN;
    const int b = t / NN;

    ull acc[8];
#pragma unroll
    for (int h2 = 0; h2 < 8; h2++) acc[h2] = 0ULL;
    float sum = 0.f, sumsq = 0.f;

    for (int ct = 0; ct < CZ/32; ct++) {
#pragma unroll
        for (int u = 0; u < 8; u++) {
            const int idx = u * 256 + tid;
            const int r = idx >> 3, q = idx & 7;
            *(float4*)&zt[r][q*4] =
                *(const float4*)&z[(size_t)(row0 + r)*CZ + ct*32 + q*4];
        }
        __syncthreads();

#pragma unroll
        for (int cq = 0; cq < 8; cq++) {
            float4 zv = *(const float4*)&zt[tid][cq*4];
            float zz[4] = {zv.x, zv.y, zv.z, zv.w};
#pragma unroll
            for (int u = 0; u < 4; u++) {
                const int c = ct*32 + cq*4 + u;
                float zc = zz[u];
                sum += zc;
                sumsq = fmaf(zc, zc, sumsq);
                ull zd = dup2(zc);
                const ulonglong2* ap = (const ulonglong2*)&A2[c][0];
                ulonglong2 a01 = ap[0], a23 = ap[1], a45 = ap[2], a67 = ap[3];
                fma2(acc[0], zd, a01.x); fma2(acc[1], zd, a01.y);
                fma2(acc[2], zd, a23.x); fma2(acc[3], zd, a23.y);
                fma2(acc[4], zd, a45.x); fma2(acc[5], zd, a45.y);
                fma2(acc[6], zd, a67.x); fma2(acc[7], zd, a67.y);
            }
        }
        __syncthreads();
    }

    const float inv = 1.f / CZ;
    float mu   = sum * inv;
    float var  = sumsq * inv - mu*mu;
    float rstd = rsqrtf(var + 1e-5f);

    const size_t base = ((size_t)b*HH*NN + i) * NN + j;
    const size_t hs   = (size_t)NN * NN;
#pragma unroll
    for (int h2 = 0; h2 < 8; h2++) {
        float d0, d1; unpack2(acc[h2], d0, d1);
        g_bias[base + (size_t)(2*h2)  *hs] = rstd*(d0 - mu*Sf[2*h2])   + Cf[2*h2];
        g_bias[base + (size_t)(2*h2+1)*hs] = rstd*(d1 - mu*Sf[2*h2+1]) + Cf[2*h2+1];
    }
}

__device__ __forceinline__ float shfl_max16(float v) {
    v = fmaxf(v, __shfl_xor_sync(0xffffffffu, v, 8));
    v = fmaxf(v, __shfl_xor_sync(0xffffffffu, v, 4));
    v = fmaxf(v, __shfl_xor_sync(0xffffffffu, v, 2));
    v = fmaxf(v, __shfl_xor_sync(0xffffffffu, v, 1));
    return v;
}
__device__ __forceinline__ float shfl_sum16(float v) {
    v += __shfl_xor_sync(0xffffffffu, v, 8);
    v += __shfl_xor_sync(0xffffffffu, v, 4);
    v += __shfl_xor_sync(0xffffffffu, v, 2);
    v += __shfl_xor_sync(0xffffffffu, v, 1);
    return v;
}

// K3: flash attention with pair bias + mask + gating.
// NEW vs R12: k/v tiles register-prefetched one tile ahead (LDG issued after
// S-compute, consumed next loop top — latency hidden under softmax+PV), and
// bias/mask prefetched at tile start (consumed after S-compute).
__global__ void __launch_bounds__(256, 2) attn_kernel(const float* __restrict__ mask)
{
    extern __shared__ float sm[];
    float* qs = sm;                       // [48][64]
    float* ks = sm + 48*IT;               // [48][64]
    float* vs = ks + 48*JT;               // [64][48]
    float* ps = vs + JT*48;               // [64][PSS]
    float* scale_s = ps + IT*PSS;         // [64]
    float* l_s = scale_s + IT;            // [64]

    const int tid = threadIdx.x;
    const int h  = blockIdx.y & (HH-1);
    const int b  = blockIdx.y >> 4;
    const int i0 = blockIdx.x * IT;
    const int tx = tid & 15, ty = tid >> 4;   // S layout: 4 rows x 4 cols
    const int tx2 = tid & 7, ty2 = tid >> 3;  // PV layout: 2 rows x 6 cols

    // k/v loader indices (3 float4 of k + 3 of v per thread per tile)
    int ldj[3], lddq[3];
#pragma unroll
    for (int u = 0; u < 3; u++) {
        const int idx = tid + u * 256;
        ldj[u]  = idx / (HD/4);
        lddq[u] = idx % (HD/4);
    }

    // load q tile transposed (once)
    for (int idx = tid; idx < IT * (HD/4); idx += 256) {
        const int r = idx / (HD/4), dq = idx % (HD/4);
        float4 v = *(const float4*)&g_q[((size_t)(b*NN + i0 + r))*CS + h*HD + dq*4];
        qs[(dq*4+0)*IT + r] = v.x; qs[(dq*4+1)*IT + r] = v.y;
        qs[(dq*4+2)*IT + r] = v.z; qs[(dq*4+3)*IT + r] = v.w;
    }

    // preload tile 0 k/v into registers
    float4 kреg[3], vreg[3];
#pragma unroll
    for (int u = 0; u < 3; u++) {
        const size_t go = ((size_t)(b*NN + ldj[u]))*CS + h*HD + lddq[u]*4;
        kреg[u] = *(const float4*)&g_k[go];
        vreg[u] = *(const float4*)&g_v[go];
    }

    float mrow[4] = {-1e30f, -1e30f, -1e30f, -1e30f};
    float lrow[4] = {0.f, 0.f, 0.f, 0.f};
    ull oacc[2][3];
#pragma unroll
    for (int r = 0; r < 2; r++)
#pragma unroll
        for (int c = 0; c < 3; c++) oacc[r][c] = 0ULL;

    const size_t bh = ((size_t)b*HH + h) * (size_t)NN * NN;
    const float scale = 0.14433756729740643f;

    for (int jt = 0; jt < NJT; jt++) {
        const int j0 = jt * JT;
        __syncthreads();   // prev PV done with ks/vs/ps

        // store prefetched k/v tile to smem
#pragma unroll
        for (int u = 0; u < 3; u++) {
            const int j = ldj[u], dq = lddq[u];
            ks[(dq*4+0)*JT + j] = kреg[u].x; ks[(dq*4+1)*JT + j] = kреg[u].y;
            ks[(dq*4+2)*JT + j] = kреg[u].z; ks[(dq*4+3)*JT + j] = kреg[u].w;
            *(float4*)&vs[j*48 + dq*4] = vreg[u];
        }

        // prefetch bias + mask for this tile (consumed after S-compute)
        float4 bias4[4];
#pragma unroll
        for (int i = 0; i < 4; i++)
            bias4[i] = *(const float4*)&g_bias[bh + (size_t)(i0+ty*4+i)*NN + j0 + tx*4];
        float4 mk = *(const float4*)&mask[b*NN + j0 + tx*4];

        __syncthreads();

        // ---- S phase ----
        ull acc[4][2];
#pragma unroll
        for (int i = 0; i < 4; i++) { acc[i][0] = 0ULL; acc[i][1] = 0ULL; }

#pragma unroll 4
        for (int d = 0; d < HD; d++) {
            float4 a = *(const float4*)&qs[d*IT + ty*4];
            ulonglong2 kb = *(const ulonglong2*)&ks[d*JT + tx*4];
            float av[4] = {a.x, a.y, a.z, a.w};
#pragma unroll
            for (int i = 0; i < 4; i++) {
                ull ad = dup2(av[i]);
                fma2(acc[i][0], ad, kb.x);
                fma2(acc[i][1], ad, kb.y);
            }
        }

        // issue LDG for next tile's k/v (latency hidden under softmax + PV)
        if (jt + 1 < NJT) {
            const int j0n = (jt + 1) * JT;
#pragma unroll
            for (int u = 0; u < 3; u++) {
                const size_t go = ((size_t)(b*NN + j0n + ldj[u]))*CS + h*HD + lddq[u]*4;
                kреg[u] = *(const float4*)&g_k[go];
                vreg[u] = *(const float4*)&g_v[go];
            }
        }

        float madd[4] = {(1.f-mk.x)*(-1e6f), (1.f-mk.y)*(-1e6f),
                         (1.f-mk.z)*(-1e6f), (1.f-mk.w)*(-1e6f)};

#pragma unroll
        for (int i = 0; i < 4; i++) {
            const int row = ty*4 + i;
            float sv[4];
            unpack2(acc[i][0], sv[0], sv[1]);
            unpack2(acc[i][1], sv[2], sv[3]);
            sv[0] = fmaf(sv[0], scale, bias4[i].x + madd[0]);
            sv[1] = fmaf(sv[1], scale, bias4[i].y + madd[1]);
            sv[2] = fmaf(sv[2], scale, bias4[i].z + madd[2]);
            sv[3] = fmaf(sv[3], scale, bias4[i].w + madd[3]);

            float rm = fmaxf(fmaxf(sv[0], sv[1]), fmaxf(sv[2], sv[3]));
            rm = shfl_max16(rm);
            float mn = fmaxf(mrow[i], rm);
            float p0 = __expf(sv[0] - mn), p1 = __expf(sv[1] - mn);
            float p2 = __expf(sv[2] - mn), p3 = __expf(sv[3] - mn);
            float rs = shfl_sum16(p0 + p1 + p2 + p3);
            float sc = __expf(mrow[i] - mn);
            lrow[i] = lrow[i] * sc + rs;
            mrow[i] = mn;
            *(float4*)&ps[row*PSS + tx*4] = make_float4(p0, p1, p2, p3);
            if (tx == 0) scale_s[row] = sc;
        }
        __syncthreads();

        // ---- PV phase: 2 rows x 6 cols per thread ----
        {
            const int r0 = ty2*2, r1 = ty2*2 + 1;
            ull d0 = dup2(scale_s[r0]);
            ull d1 = dup2(scale_s[r1]);
#pragma unroll
            for (int c = 0; c < 3; c++) { mul2(oacc[0][c], d0); mul2(oacc[1][c], d1); }

            const float* vbase = vs + tx2*6;
#pragma unroll 4
            for (int k = 0; k < JT; k += 2) {
                ull pk0 = *(const ull*)&ps[r0*PSS + k];
                ull pk1 = *(const ull*)&ps[r1*PSS + k];
                float p00, p01, p10, p11;
                unpack2(pk0, p00, p01);
                unpack2(pk1, p10, p11);
                const float* v0 = vbase + k*48;
                const float* v1 = v0 + 48;
                ull va0 = *(const ull*)(v0);
                ull va1 = *(const ull*)(v0 + 2);
                ull va2 = *(const ull*)(v0 + 4);
                ull vb0 = *(const ull*)(v1);
                ull vb1 = *(const ull*)(v1 + 2);
                ull vb2 = *(const ull*)(v1 + 4);
                ull a00 = dup2(p00), a10 = dup2(p10);
                fma2(oacc[0][0], a00, va0); fma2(oacc[0][1], a00, va1); fma2(oacc[0][2], a00, va2);
                fma2(oacc[1][0], a10, va0); fma2(oacc[1][1], a10, va1); fma2(oacc[1][2], a10, va2);
                ull a01 = dup2(p01), a11 = dup2(p11);
                fma2(oacc[0][0], a01, vb0); fma2(oacc[0][1], a01, vb1); fma2(oacc[0][2], a01, vb2);
                fma2(oacc[1][0], a11, vb0); fma2(oacc[1][1], a11, vb1); fma2(oacc[1][2], a11, vb2);
            }
        }
    }

    if (tx == 0) {
#pragma unroll
        for (int i = 0; i < 4; i++) l_s[ty*4 + i] = lrow[i];
    }
    __syncthreads();

#pragma unroll
    for (int r = 0; r < 2; r++) {
        const int row = ty2*2 + r;
        const float inv = 1.f / l_s[row];
        const size_t off = ((size_t)(b*NN + i0 + row))*CS + h*HD + tx2*6;
#pragma unroll
        for (int c = 0; c < 3; c++) {
            float o0, o1;
            unpack2(oacc[r][c], o0, o1);
            float gg0 = g_g[off + 2*c], gg1 = g_g[off + 2*c + 1];
            *(ull*)&g_og[off + 2*c] = pack2(o0 * inv * gg0, o1 * inv * gg1);
        }
    }
}

extern "C" void kernel_launch(void* const* d_in, const int* in_sizes, int n_in,
                              void* d_out, int out_size)
{
    const float* s    = (const float*)d_in[0];
    const float* z    = (const float*)d_in[1];
    const float* mask = (const float*)d_in[2];
    const float* kin  = (const float*)d_in[3];
    const float* Wq   = (const float*)d_in[4];
    const float* bq   = (const float*)d_in[5];
    const float* Wk   = (const float*)d_in[6];
    const float* Wv   = (const float*)d_in[7];
    const float* Wg   = (const float*)d_in[8];
    const float* lng  = (const float*)d_in[9];
    const float* lnb  = (const float*)d_in[10];
    const float* Wz   = (const float*)d_in[11];
    const float* Wo   = (const float*)d_in[12];
    float* out = (float*)d_out;

    const int attn_smem = (48*IT + 48*JT + JT*48 + IT*PSS + IT + IT) * 4;
    cudaFuncSetAttribute(attn_kernel,
                         cudaFuncAttributeMaxDynamicSharedMemorySize, attn_smem);

    // fork: biasproj (DRAM-bound) concurrent with qkvg (fma-bound).
    // stream/events intentionally leaked (destroy during capture invalidates it).
    cudaStream_t s2;
    cudaStreamCreateWithFlags(&s2, cudaStreamNonBlocking);
    cudaEvent_t eFork, eJoin;
    cudaEventCreateWithFlags(&eFork, cudaEventDisableTiming);
    cudaEventCreateWithFlags(&eJoin, cudaEventDisableTiming);

    cudaEventRecord(eFork, 0);
    cudaStreamWaitEvent(s2, eFork, 0);

    qkvg_kernel<<<dim3(CS/128, BB*NN/128, 4), 256>>>(s, kin, Wq, bq, Wk, Wv, Wg);
    biasproj_kernel<<<BB*NN*NN/256, 256, 0, s2>>>(z, lng, lnb, Wz);

    cudaEventRecord(eJoin, s2);
    cudaStreamWaitEvent(0, eJoin, 0);

    attn_kernel<<<dim3(NN/IT, BB*HH), 256, attn_smem>>>(mask);
    outproj_partial_kernel<<<dim3(CS/128, BB*NN/128, 4), 256>>>(Wo);
    reduce4_kernel<<<(BB*NN*CS/4)/256, 256>>>(out);
}